// round 2
// baseline (speedup 1.0000x reference)
#include <cuda_runtime.h>

#define BB 2
#define TT 16
#define NN 256
#define MM 1152
#define HH 16
#define DD 72
#define ROWS 8192           // B*T*N
#define ADAW 6912
#define QKVW 3456
#define MLPW 4608
#define SCALE 0.11785113019775793f   // 72^-0.5

// ---------------- scratch (device globals; no allocations allowed) ----------
__device__ float g_x4[ROWS * MM];      // running residual state, (B,T,N,M)
__device__ float g_ln[ROWS * MM];      // LN outputs / GEMM temporaries
__device__ float g_attn[ROWS * MM];    // attention outputs
__device__ float g_big[(size_t)ROWS * MLPW]; // qkv (3456 cols) / mlp hidden (4608)
__device__ float g_ada[BB * ADAW];
__device__ float g_tk[BB * TT * MM];   // c @ t_k (raw, pre-rotary)
__device__ float g_tv[BB * TT * MM];
__device__ float g_sk[BB * TT * MM];
__device__ float g_sv[BB * TT * MM];
__device__ float g_ropec[TT * (DD / 2)];
__device__ float g_ropes[TT * (DD / 2)];

// ---------------- ada = silu(c4t) @ W_ada + b_ada ---------------------------
__global__ __launch_bounds__(128) void ada_kernel(
    const float* __restrict__ c4t, const float* __restrict__ W,
    const float* __restrict__ bias)
{
    __shared__ float ss[MM];
    int b = blockIdx.y;
    for (int i = threadIdx.x; i < MM; i += 128) {
        float v = c4t[b * MM + i];
        ss[i] = v / (1.f + expf(-v));
    }
    __syncthreads();
    int col = blockIdx.x * 128 + threadIdx.x;
    float acc = bias[col];
    for (int k = 0; k < MM; k++)
        acc += ss[k] * W[(size_t)k * ADAW + col];
    g_ada[b * ADAW + col] = acc;
}

// ---------------- rope tables (pos = f[t]) ----------------------------------
__global__ void rope_kernel(const int* __restrict__ f)
{
    int idx = threadIdx.x;
    if (idx < TT * (DD / 2)) {
        int t = idx / (DD / 2), i = idx % (DD / 2);
        float pos = (float)f[t];
        float freq = powf(10000.f, -((2.f * (float)i) / (float)DD));
        float a = pos * freq;
        g_ropec[idx] = cosf(a);
        g_ropes[idx] = sinf(a);
    }
}

// ---------------- extra-KV projections: c @ {t_k,t_v,s_k,s_v} ---------------
__global__ __launch_bounds__(256) void ekv_kernel(
    const float* __restrict__ c,
    const float* __restrict__ tk, const float* __restrict__ tv,
    const float* __restrict__ sk, const float* __restrict__ sv)
{
    __shared__ float cs[MM];
    int row = blockIdx.x;           // (b*T + t), 0..31
    int which = blockIdx.y;         // 0..3
    const float* W = (which == 0) ? tk : (which == 1) ? tv : (which == 2) ? sk : sv;
    float* O = (which == 0) ? g_tk : (which == 1) ? g_tv : (which == 2) ? g_sk : g_sv;
    for (int i = threadIdx.x; i < MM; i += 256) cs[i] = c[(size_t)row * MM + i];
    __syncthreads();
    for (int col = threadIdx.x; col < MM; col += 256) {
        float acc = 0.f;
        for (int k = 0; k < MM; k++)
            acc += cs[k] * W[(size_t)k * MM + col];
        O[(size_t)row * MM + col] = acc;
    }
}

// ---------------- LayerNorm (+affine or adaLN modulation, optional permute) -
__global__ __launch_bounds__(256) void ln_kernel(
    const float* __restrict__ X, float* __restrict__ out, float* __restrict__ copyDst,
    const float* __restrict__ w, const float* __restrict__ bvec,
    const float* __restrict__ ada, int shOff, int scOff, float eps, int permute)
{
    int row = blockIdx.x;           // input row order: (b, t, n)
    const float* xr = X + (size_t)row * MM;
    float xv[5];
    float s = 0.f, sq = 0.f;
    int k = 0;
    for (int i = threadIdx.x; i < MM; i += 256, k++) {
        float v = xr[i];
        xv[k] = v;
        s += v; sq += v * v;
    }
    __shared__ float reds[8], redq[8], stats[2];
    for (int off = 16; off > 0; off >>= 1) {
        s  += __shfl_xor_sync(0xffffffffu, s,  off);
        sq += __shfl_xor_sync(0xffffffffu, sq, off);
    }
    int wid = threadIdx.x >> 5, lane = threadIdx.x & 31;
    if (lane == 0) { reds[wid] = s; redq[wid] = sq; }
    __syncthreads();
    if (threadIdx.x == 0) {
        float ts = 0.f, tq = 0.f;
        for (int i2 = 0; i2 < 8; i2++) { ts += reds[i2]; tq += redq[i2]; }
        float mean = ts * (1.f / MM);
        float var = tq * (1.f / MM) - mean * mean;
        stats[0] = mean;
        stats[1] = rsqrtf(var + eps);
    }
    __syncthreads();
    float mean = stats[0], rstd = stats[1];
    int b = row >> 12;
    int orow = row;
    if (permute) {                  // (b,t,n) -> (b,n,t)
        int rem = row & 4095;
        int t = rem >> 8, n = rem & 255;
        orow = ((b << 8) + n) * TT + t;
    }
    k = 0;
    for (int i = threadIdx.x; i < MM; i += 256, k++) {
        float v = xv[k];
        float nv = (v - mean) * rstd;
        float y;
        if (ada) y = nv * (1.f + ada[b * ADAW + scOff + i]) + ada[b * ADAW + shOff + i];
        else     y = nv * w[i] + bvec[i];
        out[(size_t)orow * MM + i] = y;
        if (copyDst) copyDst[(size_t)row * MM + i] = v;
    }
}

// ---------------- generic SGEMM 128x128x8, 8x8 microtile --------------------
// C[orow] = (addsrc? addsrc : 0) + gate * act(A@W + bias)
__global__ __launch_bounds__(256) void sgemm_kernel(
    const float* __restrict__ A, const float* __restrict__ W,
    const float* __restrict__ bias, const float* __restrict__ addsrc,
    const float* __restrict__ gate,
    float* __restrict__ C, int K, int Nc, int act, int permute)
{
    __shared__ float As[8][128];
    __shared__ float Bs[8][128];
    int tid = threadIdx.x;
    int blockRow = blockIdx.y * 128;
    int blockCol = blockIdx.x * 128;
    int ar = tid >> 1, ac = (tid & 1) << 2;
    int br = tid >> 5, bc = (tid & 31) << 2;
    int ty = tid >> 4, tx = tid & 15;
    const float* Aptr = A + (size_t)(blockRow + ar) * K + ac;
    const float* Bptr = W + (size_t)br * Nc + blockCol + bc;
    float acc[8][8];
#pragma unroll
    for (int i = 0; i < 8; i++)
#pragma unroll
        for (int j = 0; j < 8; j++) acc[i][j] = 0.f;

    for (int k0 = 0; k0 < K; k0 += 8) {
        float4 av = *(const float4*)Aptr;
        float4 bv = *(const float4*)Bptr;
        Aptr += 8;
        Bptr += (size_t)8 * Nc;
        As[ac + 0][ar] = av.x; As[ac + 1][ar] = av.y;
        As[ac + 2][ar] = av.z; As[ac + 3][ar] = av.w;
        *(float4*)&Bs[br][bc] = bv;
        __syncthreads();
#pragma unroll
        for (int k = 0; k < 8; k++) {
            float4 a0 = *(const float4*)&As[k][ty * 8];
            float4 a1 = *(const float4*)&As[k][ty * 8 + 4];
            float4 b0 = *(const float4*)&Bs[k][tx * 8];
            float4 b1 = *(const float4*)&Bs[k][tx * 8 + 4];
            float a[8] = {a0.x, a0.y, a0.z, a0.w, a1.x, a1.y, a1.z, a1.w};
            float b[8] = {b0.x, b0.y, b0.z, b0.w, b1.x, b1.y, b1.z, b1.w};
#pragma unroll
            for (int i = 0; i < 8; i++)
#pragma unroll
                for (int j = 0; j < 8; j++)
                    acc[i][j] += a[i] * b[j];
        }
        __syncthreads();
    }

#pragma unroll
    for (int i = 0; i < 8; i++) {
        int row = blockRow + ty * 8 + i;
        int orow = row;
        if (permute) {              // rows (b,n,t) -> (b,t,n)
            int b = row >> 12, rem = row & 4095;
            int n = rem >> 4, t = rem & 15;
            orow = ((b << 4) + t) * NN + n;
        }
        int bch = row >> 12;
#pragma unroll
        for (int j = 0; j < 8; j++) {
            int col = blockCol + tx * 8 + j;
            float v = acc[i][j];
            if (bias) v += bias[col];
            if (act == 1) {
                float xg = v;
                v = 0.5f * xg * (1.f + tanhf(0.7978845608028654f *
                        (xg + 0.044715f * xg * xg * xg)));
            }
            if (gate) v *= gate[bch * ADAW + col];
            if (addsrc) v += addsrc[(size_t)orow * Nc + col];
            C[(size_t)orow * Nc + col] = v;
        }
    }
}

// ---------------- temporal attention: per (b,n,h), T=16, KV=32 --------------
__global__ __launch_bounds__(256) void attn_t_kernel()
{
    __shared__ float qs[TT * DD];
    __shared__ float kks[2 * TT * DD];
    __shared__ float vvs[2 * TT * DD];
    __shared__ float scs[TT * 2 * TT];
    int h = blockIdx.x, n = blockIdx.y, b = blockIdx.z;
    const float* base = g_big + (size_t)((b * NN + n) * TT) * QKVW + h * DD;

    // load + rotary on q (scaled), k, ek (pairs)
    for (int idx = threadIdx.x; idx < TT * (DD / 2); idx += 256) {
        int t = idx / (DD / 2), i = idx % (DD / 2);
        float cc = g_ropec[idx], ssn = g_ropes[idx];
        const float* qr = base + (size_t)t * QKVW + 2 * i;
        float x0 = qr[0], x1 = qr[1];
        qs[t * DD + 2 * i]     = SCALE * (x0 * cc - x1 * ssn);
        qs[t * DD + 2 * i + 1] = SCALE * (x1 * cc + x0 * ssn);
        const float* kr = qr + MM;
        x0 = kr[0]; x1 = kr[1];
        kks[(TT + t) * DD + 2 * i]     = x0 * cc - x1 * ssn;
        kks[(TT + t) * DD + 2 * i + 1] = x1 * cc + x0 * ssn;
        const float* er = g_tk + (size_t)(b * TT + t) * MM + h * DD + 2 * i;
        x0 = er[0]; x1 = er[1];
        kks[t * DD + 2 * i]     = x0 * cc - x1 * ssn;
        kks[t * DD + 2 * i + 1] = x1 * cc + x0 * ssn;
    }
    for (int idx = threadIdx.x; idx < TT * DD; idx += 256) {
        int t = idx / DD, d = idx % DD;
        vvs[(TT + t) * DD + d] = base[(size_t)t * QKVW + 2 * MM + d];
        vvs[t * DD + d] = g_tv[(size_t)(b * TT + t) * MM + h * DD + d];
    }
    __syncthreads();

    for (int idx = threadIdx.x; idx < TT * 2 * TT; idx += 256) {
        int t = idx / (2 * TT), j = idx % (2 * TT);
        float acc = 0.f;
#pragma unroll
        for (int d = 0; d < DD; d++) acc += qs[t * DD + d] * kks[j * DD + d];
        scs[idx] = acc;
    }
    __syncthreads();

    if (threadIdx.x < TT) {
        int t = threadIdx.x;
        float m = -1e30f;
        for (int j = 0; j < 2 * TT; j++) m = fmaxf(m, scs[t * 2 * TT + j]);
        float sum = 0.f;
        for (int j = 0; j < 2 * TT; j++) {
            float p = expf(scs[t * 2 * TT + j] - m);
            scs[t * 2 * TT + j] = p;
            sum += p;
        }
        float inv = 1.f / sum;
        for (int j = 0; j < 2 * TT; j++) scs[t * 2 * TT + j] *= inv;
    }
    __syncthreads();

    for (int idx = threadIdx.x; idx < TT * DD; idx += 256) {
        int t = idx / DD, d = idx % DD;
        float acc = 0.f;
#pragma unroll
        for (int j = 0; j < 2 * TT; j++) acc += scs[t * 2 * TT + j] * vvs[j * DD + d];
        g_attn[(size_t)((b * NN + n) * TT + t) * MM + h * DD + d] = acc;
    }
}

// ---------------- spatial attention: per (b,t,h), N=256 queries, KV=257 -----
__global__ __launch_bounds__(256) void attn_s_kernel()
{
    int h = blockIdx.x, t = blockIdx.y, b = blockIdx.z;
    int n = threadIdx.x;
    const float* base = g_big + (size_t)((b * TT + t) * NN) * QKVW;
    const float* qrow = base + (size_t)n * QKVW + h * DD;
    float q[DD];
#pragma unroll
    for (int i = 0; i < DD / 4; i++) {
        float4 v = ((const float4*)qrow)[i];
        q[4 * i + 0] = v.x * SCALE; q[4 * i + 1] = v.y * SCALE;
        q[4 * i + 2] = v.z * SCALE; q[4 * i + 3] = v.w * SCALE;
    }
    float sc[NN + 1];
    float m;
    {
        const float4* kr = (const float4*)(g_sk + (size_t)(b * TT + t) * MM + h * DD);
        float s = 0.f;
#pragma unroll
        for (int i = 0; i < DD / 4; i++) {
            float4 kv = kr[i];
            s += q[4 * i] * kv.x + q[4 * i + 1] * kv.y + q[4 * i + 2] * kv.z + q[4 * i + 3] * kv.w;
        }
        sc[0] = s; m = s;
    }
    for (int j = 0; j < NN; j++) {
        const float4* kr = (const float4*)(base + (size_t)j * QKVW + MM + h * DD);
        float s = 0.f;
#pragma unroll
        for (int i = 0; i < DD / 4; i++) {
            float4 kv = kr[i];
            s += q[4 * i] * kv.x + q[4 * i + 1] * kv.y + q[4 * i + 2] * kv.z + q[4 * i + 3] * kv.w;
        }
        sc[j + 1] = s;
        m = fmaxf(m, s);
    }
    float sum = 0.f;
    for (int j = 0; j <= NN; j++) {
        float p = expf(sc[j] - m);
        sc[j] = p;
        sum += p;
    }
    float inv = 1.f / sum;
    float acc[DD];
#pragma unroll
    for (int d = 0; d < DD; d++) acc[d] = 0.f;
    {
        float p = sc[0];
        const float4* vr = (const float4*)(g_sv + (size_t)(b * TT + t) * MM + h * DD);
#pragma unroll
        for (int i = 0; i < DD / 4; i++) {
            float4 vv = vr[i];
            acc[4 * i] += p * vv.x; acc[4 * i + 1] += p * vv.y;
            acc[4 * i + 2] += p * vv.z; acc[4 * i + 3] += p * vv.w;
        }
    }
    for (int j = 0; j < NN; j++) {
        float p = sc[j + 1];
        const float4* vr = (const float4*)(base + (size_t)j * QKVW + 2 * MM + h * DD);
#pragma unroll
        for (int i = 0; i < DD / 4; i++) {
            float4 vv = vr[i];
            acc[4 * i] += p * vv.x; acc[4 * i + 1] += p * vv.y;
            acc[4 * i + 2] += p * vv.z; acc[4 * i + 3] += p * vv.w;
        }
    }
    float* orow = g_attn + (size_t)((b * TT + t) * NN + n) * MM + h * DD;
#pragma unroll
    for (int d = 0; d < DD; d++) orow[d] = acc[d] * inv;
}

// ---------------- launch ----------------------------------------------------
extern "C" void kernel_launch(void* const* d_in, const int* in_sizes, int n_in,
                              void* d_out, int out_size)
{
    (void)in_sizes; (void)n_in; (void)out_size;
    const float* x      = (const float*)d_in[0];
    const float* c4t    = (const float*)d_in[1];
    const float* c      = (const float*)d_in[2];
    const float* W_ada  = (const float*)d_in[3];
    const float* b_ada  = (const float*)d_in[4];
    const float* tn_w   = (const float*)d_in[5];
    const float* tn_b   = (const float*)d_in[6];
    const float* t_qkv  = (const float*)d_in[7];
    const float* t_k    = (const float*)d_in[8];
    const float* t_v    = (const float*)d_in[9];
    const float* t_out  = (const float*)d_in[10];
    const float* t_fc_w = (const float*)d_in[11];
    const float* t_fc_b = (const float*)d_in[12];
    const float* s_qkv  = (const float*)d_in[13];
    const float* s_k    = (const float*)d_in[14];
    const float* s_v    = (const float*)d_in[15];
    const float* s_out  = (const float*)d_in[16];
    const float* mlp_w1 = (const float*)d_in[17];
    const float* mlp_b1 = (const float*)d_in[18];
    const float* mlp_w2 = (const float*)d_in[19];
    const float* mlp_b2 = (const float*)d_in[20];
    const int*   f      = (const int*)d_in[21];
    float* out = (float*)d_out;

    float *px4, *pln, *pattn, *pbig, *pada;
    cudaGetSymbolAddress((void**)&px4,  g_x4);
    cudaGetSymbolAddress((void**)&pln,  g_ln);
    cudaGetSymbolAddress((void**)&pattn,g_attn);
    cudaGetSymbolAddress((void**)&pbig, g_big);
    cudaGetSymbolAddress((void**)&pada, g_ada);

    // prologue: ada, rope tables, extra-KV projections
    ada_kernel<<<dim3(ADAW / 128, BB), 128>>>(c4t, W_ada, b_ada);
    rope_kernel<<<1, TT * (DD / 2)>>>(f);
    ekv_kernel<<<dim3(BB * TT, 4), 256>>>(c, t_k, t_v, s_k, s_v);

    // temporal branch
    ln_kernel<<<ROWS, 256>>>(x, pln, px4, tn_w, tn_b, nullptr, 0, 0, 1e-5f, 1);
    sgemm_kernel<<<dim3(QKVW / 128, ROWS / 128), 256>>>(
        pln, t_qkv, nullptr, nullptr, nullptr, pbig, MM, QKVW, 0, 0);
    attn_t_kernel<<<dim3(HH, NN, BB), 256>>>();
    sgemm_kernel<<<dim3(MM / 128, ROWS / 128), 256>>>(
        pattn, t_out, nullptr, nullptr, nullptr, pln, MM, MM, 0, 1);
    sgemm_kernel<<<dim3(MM / 128, ROWS / 128), 256>>>(
        pln, t_fc_w, t_fc_b, px4, nullptr, px4, MM, MM, 0, 0);

    // spatial branch (adaLN modulated, gated)
    ln_kernel<<<ROWS, 256>>>(px4, pln, nullptr, nullptr, nullptr, pada, 0, MM, 1e-6f, 0);
    sgemm_kernel<<<dim3(QKVW / 128, ROWS / 128), 256>>>(
        pln, s_qkv, nullptr, nullptr, nullptr, pbig, MM, QKVW, 0, 0);
    attn_s_kernel<<<dim3(HH, TT, BB), 256>>>();
    sgemm_kernel<<<dim3(MM / 128, ROWS / 128), 256>>>(
        pattn, s_out, nullptr, px4, pada + 2 * MM, px4, MM, MM, 0, 0);

    // MLP (adaLN modulated, gated); final GEMM writes d_out directly
    ln_kernel<<<ROWS, 256>>>(px4, pln, nullptr, nullptr, nullptr, pada, 3 * MM, 4 * MM, 1e-6f, 0);
    sgemm_kernel<<<dim3(MLPW / 128, ROWS / 128), 256>>>(
        pln, mlp_w1, mlp_b1, nullptr, nullptr, pbig, MM, MLPW, 1, 0);
    sgemm_kernel<<<dim3(MM / 128, ROWS / 128), 256>>>(
        pbig, mlp_w2, mlp_b2, px4, pada + 5 * MM, out, MLPW, MM, 0, 0);
}

// round 8
// speedup vs baseline: 2.0451x; 2.0451x over previous
#include <cuda_runtime.h>
#include <cstdint>

#define BB 2
#define TT 16
#define NN 256
#define MM 1152
#define HH 16
#define DD 72
#define ROWS 8192
#define ADAW 6912
#define QKVW 3456
#define MLPW 4608
#define SCALE 0.11785113019775793f

// ---------------- scratch -----------------------------------------------
__device__ float g_x4[ROWS * MM];
__device__ float g_ln[ROWS * MM];
__device__ float g_attn[ROWS * MM];
__device__ float g_big[(size_t)ROWS * MLPW];
__device__ float g_ada[BB * ADAW];
__device__ float g_tk[BB * TT * MM];
__device__ float g_tv[BB * TT * MM];
__device__ float g_sk[BB * TT * MM];
__device__ float g_sv[BB * TT * MM];
__device__ float g_ropec[TT * (DD / 2)];
__device__ float g_ropes[TT * (DD / 2)];

// ---------------- mma.sync tf32 GEMM ------------------------------------
// CTA tile 128x128, 256 threads = 8 warps (4 x 2), warp tile 32x64.
// K-chunk 16, 2-stage cp.async double buffer.
// smem floats: As[128][20] (stride 20: banks 20q+k distinct),
//              Bs[16][136]  (stride 136: banks 8k+n distinct)
#define AS_STRIDE 20
#define BS_STRIDE 136
#define AS_SIZE (128 * AS_STRIDE)
#define BS_SIZE (16 * BS_STRIDE)
#define STAGE (AS_SIZE + BS_SIZE)
#define TCG_SMEM (2 * STAGE * 4)

__device__ __forceinline__ uint32_t f2tf32(float x) {
    uint32_t u;
    asm("cvt.rna.tf32.f32 %0, %1;" : "=r"(u) : "f"(x));
    return u;
}
__device__ __forceinline__ void cpa16(float* s, const float* g) {
    uint32_t sa;
    asm("{ .reg .u64 t; cvta.to.shared.u64 t, %1; cvt.u32.u64 %0, t; }"
        : "=r"(sa) : "l"(s));
    asm volatile("cp.async.cg.shared.global [%0], [%1], 16;" :: "r"(sa), "l"(g));
}
__device__ __forceinline__ void mma1688(float* d, const uint32_t* a, const uint32_t* b) {
    asm volatile(
        "mma.sync.aligned.m16n8k8.row.col.f32.tf32.tf32.f32 "
        "{%0,%1,%2,%3},{%4,%5,%6,%7},{%8,%9},{%0,%1,%2,%3};"
        : "+f"(d[0]), "+f"(d[1]), "+f"(d[2]), "+f"(d[3])
        : "r"(a[0]), "r"(a[1]), "r"(a[2]), "r"(a[3]), "r"(b[0]), "r"(b[1]));
}

__global__ __launch_bounds__(256) void tc_gemm_kernel(
    const float* __restrict__ A, const float* __restrict__ W,
    const float* __restrict__ bias, const float* __restrict__ addsrc,
    const float* __restrict__ gate, float* __restrict__ C,
    int K, int Nc, int act, int permute)
{
    extern __shared__ float smem[];
    int tid = threadIdx.x, lane = tid & 31, wid = tid >> 5;
    int wm = wid & 3, wn = wid >> 2;
    int qrow = lane >> 2, qk = lane & 3;
    int blockCol = blockIdx.x * 128, blockRow = blockIdx.y * 128;
    int nc = K >> 4;

    float acc[2][8][4];
#pragma unroll
    for (int mt = 0; mt < 2; mt++)
#pragma unroll
        for (int nt = 0; nt < 8; nt++)
#pragma unroll
            for (int r = 0; r < 4; r++) acc[mt][nt][r] = 0.f;

    // cp.async index plan: A chunk 128x16 = 512 float4, B chunk 16x128 = 512 float4
    int ai0 = tid * 2;            // A float4 ids {ai0, ai0+1}
    int arow0 = ai0 >> 2,  ac40 = ai0 & 3;
    int arow1 = (ai0 + 1) >> 2, ac41 = (ai0 + 1) & 3;
    int brow0 = ai0 >> 5,  bc40 = ai0 & 31;
    int brow1 = (ai0 + 1) >> 5, bc41 = (ai0 + 1) & 31;

    const float* Abase = A + (size_t)blockRow * K;
    const float* Wbase = W + blockCol;

#define PREFETCH(chunk, stg) do {                                              \
    float* As = smem + (stg) * STAGE;                                           \
    float* Bs = As + AS_SIZE;                                                   \
    int k0 = (chunk) << 4;                                                      \
    cpa16(As + arow0 * AS_STRIDE + ac40 * 4,                                    \
          Abase + (size_t)arow0 * K + k0 + ac40 * 4);                           \
    cpa16(As + arow1 * AS_STRIDE + ac41 * 4,                                    \
          Abase + (size_t)arow1 * K + k0 + ac41 * 4);                           \
    cpa16(Bs + brow0 * BS_STRIDE + bc40 * 4,                                    \
          Wbase + (size_t)(k0 + brow0) * Nc + bc40 * 4);                        \
    cpa16(Bs + brow1 * BS_STRIDE + bc41 * 4,                                    \
          Wbase + (size_t)(k0 + brow1) * Nc + bc41 * 4);                        \
    asm volatile("cp.async.commit_group;" ::: "memory");                        \
} while (0)

    PREFETCH(0, 0);

#pragma unroll 1
    for (int i = 0; i < nc; i++) {
        if (i + 1 < nc) {
            PREFETCH(i + 1, (i + 1) & 1);
            asm volatile("cp.async.wait_group 1;" ::: "memory");
        } else {
            asm volatile("cp.async.wait_group 0;" ::: "memory");
        }
        __syncthreads();
        const float* As = smem + (i & 1) * STAGE;
        const float* Bs = As + AS_SIZE;
#pragma unroll
        for (int kk = 0; kk < 2; kk++) {
            int kb = kk * 8;
            uint32_t a[2][4], b[8][2];
#pragma unroll
            for (int mt = 0; mt < 2; mt++) {
                int m = wm * 32 + mt * 16 + qrow;
                a[mt][0] = f2tf32(As[m * AS_STRIDE + kb + qk]);
                a[mt][1] = f2tf32(As[(m + 8) * AS_STRIDE + kb + qk]);
                a[mt][2] = f2tf32(As[m * AS_STRIDE + kb + qk + 4]);
                a[mt][3] = f2tf32(As[(m + 8) * AS_STRIDE + kb + qk + 4]);
            }
#pragma unroll
            for (int nt = 0; nt < 8; nt++) {
                int n = wn * 64 + nt * 8 + qrow;
                b[nt][0] = f2tf32(Bs[(kb + qk) * BS_STRIDE + n]);
                b[nt][1] = f2tf32(Bs[(kb + qk + 4) * BS_STRIDE + n]);
            }
#pragma unroll
            for (int mt = 0; mt < 2; mt++)
#pragma unroll
                for (int nt = 0; nt < 8; nt++)
                    mma1688(acc[mt][nt], a[mt], b[nt]);
        }
        __syncthreads();
    }

    // epilogue: fragment layout d0:(r,c) d1:(r,c+1) d2:(r+8,c) d3:(r+8,c+1)
#pragma unroll
    for (int mt = 0; mt < 2; mt++) {
#pragma unroll
        for (int half = 0; half < 2; half++) {
            int row = blockRow + wm * 32 + mt * 16 + qrow + half * 8;
            int bch = row >> 12;
            int orow = row;
            if (permute) {
                int rem = row & 4095;
                orow = ((bch << 4) + (rem & 15)) * NN + (rem >> 4);
            }
            float* crow = C + (size_t)orow * Nc;
            const float* arow = addsrc ? addsrc + (size_t)orow * Nc : nullptr;
#pragma unroll
            for (int nt = 0; nt < 8; nt++) {
#pragma unroll
                for (int e = 0; e < 2; e++) {
                    int col = blockCol + wn * 64 + nt * 8 + 2 * qk + e;
                    float v = acc[mt][nt][half * 2 + e];
                    if (bias) v += bias[col];
                    if (act) {
                        float xg = v;
                        v = 0.5f * xg * (1.f + tanhf(0.7978845608028654f *
                                (xg + 0.044715f * xg * xg * xg)));
                    }
                    if (gate) v *= gate[bch * ADAW + col];
                    if (arow) v += arow[col];
                    crow[col] = v;
                }
            }
        }
    }
}

// ---------------- ada = silu(c4t) @ W_ada + b_ada -------------------------
__global__ __launch_bounds__(128) void ada_kernel(
    const float* __restrict__ c4t, const float* __restrict__ W,
    const float* __restrict__ bias)
{
    __shared__ float ss[MM];
    int b = blockIdx.y;
    for (int i = threadIdx.x; i < MM; i += 128) {
        float v = c4t[b * MM + i];
        ss[i] = v / (1.f + expf(-v));
    }
    __syncthreads();
    int col = blockIdx.x * 128 + threadIdx.x;
    float acc = bias[col];
    for (int k = 0; k < MM; k++)
        acc += ss[k] * W[(size_t)k * ADAW + col];
    g_ada[b * ADAW + col] = acc;
}

// ---------------- rope tables ---------------------------------------------
__global__ void rope_kernel(const int* __restrict__ f)
{
    int idx = threadIdx.x;
    if (idx < TT * (DD / 2)) {
        int t = idx / (DD / 2), i = idx % (DD / 2);
        float pos = (float)f[t];
        float freq = powf(10000.f, -((2.f * (float)i) / (float)DD));
        float a = pos * freq;
        g_ropec[idx] = cosf(a);
        g_ropes[idx] = sinf(a);
    }
}

// ---------------- extra-KV projections ------------------------------------
__global__ __launch_bounds__(256) void ekv_kernel(
    const float* __restrict__ c,
    const float* __restrict__ tk, const float* __restrict__ tv,
    const float* __restrict__ sk, const float* __restrict__ sv)
{
    __shared__ float cs[MM];
    int row = blockIdx.x;
    int which = blockIdx.y;
    const float* W = (which == 0) ? tk : (which == 1) ? tv : (which == 2) ? sk : sv;
    float* O = (which == 0) ? g_tk : (which == 1) ? g_tv : (which == 2) ? g_sk : g_sv;
    for (int i = threadIdx.x; i < MM; i += 256) cs[i] = c[(size_t)row * MM + i];
    __syncthreads();
    for (int col = threadIdx.x; col < MM; col += 256) {
        float acc = 0.f;
        for (int k = 0; k < MM; k++)
            acc += cs[k] * W[(size_t)k * MM + col];
        O[(size_t)row * MM + col] = acc;
    }
}

// ---------------- LayerNorm ------------------------------------------------
__global__ __launch_bounds__(256) void ln_kernel(
    const float* __restrict__ X, float* __restrict__ out, float* __restrict__ copyDst,
    const float* __restrict__ w, const float* __restrict__ bvec,
    const float* __restrict__ ada, int shOff, int scOff, float eps, int permute)
{
    int row = blockIdx.x;
    const float* xr = X + (size_t)row * MM;
    float xv[5];
    float s = 0.f, sq = 0.f;
    int k = 0;
    for (int i = threadIdx.x; i < MM; i += 256, k++) {
        float v = xr[i];
        xv[k] = v;
        s += v; sq += v * v;
    }
    __shared__ float reds[8], redq[8], stats[2];
    for (int off = 16; off > 0; off >>= 1) {
        s  += __shfl_xor_sync(0xffffffffu, s,  off);
        sq += __shfl_xor_sync(0xffffffffu, sq, off);
    }
    int wid = threadIdx.x >> 5, lane = threadIdx.x & 31;
    if (lane == 0) { reds[wid] = s; redq[wid] = sq; }
    __syncthreads();
    if (threadIdx.x == 0) {
        float ts = 0.f, tq = 0.f;
        for (int i2 = 0; i2 < 8; i2++) { ts += reds[i2]; tq += redq[i2]; }
        float mean = ts * (1.f / MM);
        float var = tq * (1.f / MM) - mean * mean;
        stats[0] = mean;
        stats[1] = rsqrtf(var + eps);
    }
    __syncthreads();
    float mean = stats[0], rstd = stats[1];
    int b = row >> 12;
    int orow = row;
    if (permute) {
        int rem = row & 4095;
        int t = rem >> 8, n = rem & 255;
        orow = ((b << 8) + n) * TT + t;
    }
    k = 0;
    for (int i = threadIdx.x; i < MM; i += 256, k++) {
        float v = xv[k];
        float nv = (v - mean) * rstd;
        float y;
        if (ada) y = nv * (1.f + ada[b * ADAW + scOff + i]) + ada[b * ADAW + shOff + i];
        else     y = nv * w[i] + bvec[i];
        out[(size_t)orow * MM + i] = y;
        if (copyDst) copyDst[(size_t)row * MM + i] = v;
    }
}

// ---------------- temporal attention ---------------------------------------
__global__ __launch_bounds__(256) void attn_t_kernel()
{
    __shared__ float qs[TT * DD];
    __shared__ float kks[2 * TT * DD];
    __shared__ float vvs[2 * TT * DD];
    __shared__ float scs[TT * 2 * TT];
    int h = blockIdx.x, n = blockIdx.y, b = blockIdx.z;
    const float* base = g_big + (size_t)((b * NN + n) * TT) * QKVW + h * DD;

    for (int idx = threadIdx.x; idx < TT * (DD / 2); idx += 256) {
        int t = idx / (DD / 2), i = idx % (DD / 2);
        float cc = g_ropec[idx], ssn = g_ropes[idx];
        const float* qr = base + (size_t)t * QKVW + 2 * i;
        float x0 = qr[0], x1 = qr[1];
        qs[t * DD + 2 * i]     = SCALE * (x0 * cc - x1 * ssn);
        qs[t * DD + 2 * i + 1] = SCALE * (x1 * cc + x0 * ssn);
        const float* kr = qr + MM;
        x0 = kr[0]; x1 = kr[1];
        kks[(TT + t) * DD + 2 * i]     = x0 * cc - x1 * ssn;
        kks[(TT + t) * DD + 2 * i + 1] = x1 * cc + x0 * ssn;
        const float* er = g_tk + (size_t)(b * TT + t) * MM + h * DD + 2 * i;
        x0 = er[0]; x1 = er[1];
        kks[t * DD + 2 * i]     = x0 * cc - x1 * ssn;
        kks[t * DD + 2 * i + 1] = x1 * cc + x0 * ssn;
    }
    for (int idx = threadIdx.x; idx < TT * DD; idx += 256) {
        int t = idx / DD, d = idx % DD;
        vvs[(TT + t) * DD + d] = base[(size_t)t * QKVW + 2 * MM + d];
        vvs[t * DD + d] = g_tv[(size_t)(b * TT + t) * MM + h * DD + d];
    }
    __syncthreads();

    for (int idx = threadIdx.x; idx < TT * 2 * TT; idx += 256) {
        int t = idx / (2 * TT), j = idx % (2 * TT);
        float acc = 0.f;
#pragma unroll
        for (int d = 0; d < DD; d++) acc += qs[t * DD + d] * kks[j * DD + d];
        scs[idx] = acc;
    }
    __syncthreads();

    if (threadIdx.x < TT) {
        int t = threadIdx.x;
        float m = -1e30f;
        for (int j = 0; j < 2 * TT; j++) m = fmaxf(m, scs[t * 2 * TT + j]);
        float sum = 0.f;
        for (int j = 0; j < 2 * TT; j++) {
            float p = expf(scs[t * 2 * TT + j] - m);
            scs[t * 2 * TT + j] = p;
            sum += p;
        }
        float inv = 1.f / sum;
        for (int j = 0; j < 2 * TT; j++) scs[t * 2 * TT + j] *= inv;
    }
    __syncthreads();

    for (int idx = threadIdx.x; idx < TT * DD; idx += 256) {
        int t = idx / DD, d = idx % DD;
        float acc = 0.f;
#pragma unroll
        for (int j = 0; j < 2 * TT; j++) acc += scs[t * 2 * TT + j] * vvs[j * DD + d];
        g_attn[(size_t)((b * NN + n) * TT + t) * MM + h * DD + d] = acc;
    }
}

// ---------------- spatial attention ----------------------------------------
__global__ __launch_bounds__(256) void attn_s_kernel()
{
    int h = blockIdx.x, t = blockIdx.y, b = blockIdx.z;
    int n = threadIdx.x;
    const float* base = g_big + (size_t)((b * TT + t) * NN) * QKVW;
    const float* qrow = base + (size_t)n * QKVW + h * DD;
    float q[DD];
#pragma unroll
    for (int i = 0; i < DD / 4; i++) {
        float4 v = ((const float4*)qrow)[i];
        q[4 * i + 0] = v.x * SCALE; q[4 * i + 1] = v.y * SCALE;
        q[4 * i + 2] = v.z * SCALE; q[4 * i + 3] = v.w * SCALE;
    }
    float sc[NN + 1];
    float m;
    {
        const float4* kr = (const float4*)(g_sk + (size_t)(b * TT + t) * MM + h * DD);
        float s = 0.f;
#pragma unroll
        for (int i = 0; i < DD / 4; i++) {
            float4 kv = kr[i];
            s += q[4 * i] * kv.x + q[4 * i + 1] * kv.y + q[4 * i + 2] * kv.z + q[4 * i + 3] * kv.w;
        }
        sc[0] = s; m = s;
    }
    for (int j = 0; j < NN; j++) {
        const float4* kr = (const float4*)(base + (size_t)j * QKVW + MM + h * DD);
        float s = 0.f;
#pragma unroll
        for (int i = 0; i < DD / 4; i++) {
            float4 kv = kr[i];
            s += q[4 * i] * kv.x + q[4 * i + 1] * kv.y + q[4 * i + 2] * kv.z + q[4 * i + 3] * kv.w;
        }
        sc[j + 1] = s;
        m = fmaxf(m, s);
    }
    float sum = 0.f;
    for (int j = 0; j <= NN; j++) {
        float p = expf(sc[j] - m);
        sc[j] = p;
        sum += p;
    }
    float inv = 1.f / sum;
    float acc[DD];
#pragma unroll
    for (int d = 0; d < DD; d++) acc[d] = 0.f;
    {
        float p = sc[0];
        const float4* vr = (const float4*)(g_sv + (size_t)(b * TT + t) * MM + h * DD);
#pragma unroll
        for (int i = 0; i < DD / 4; i++) {
            float4 vv = vr[i];
            acc[4 * i] += p * vv.x; acc[4 * i + 1] += p * vv.y;
            acc[4 * i + 2] += p * vv.z; acc[4 * i + 3] += p * vv.w;
        }
    }
    for (int j = 0; j < NN; j++) {
        float p = sc[j + 1];
        const float4* vr = (const float4*)(base + (size_t)j * QKVW + 2 * MM + h * DD);
#pragma unroll
        for (int i = 0; i < DD / 4; i++) {
            float4 vv = vr[i];
            acc[4 * i] += p * vv.x; acc[4 * i + 1] += p * vv.y;
            acc[4 * i + 2] += p * vv.z; acc[4 * i + 3] += p * vv.w;
        }
    }
    float* orow = g_attn + (size_t)((b * TT + t) * NN + n) * MM + h * DD;
#pragma unroll
    for (int d = 0; d < DD; d++) orow[d] = acc[d] * inv;
}

// ---------------- launch ----------------------------------------------------
extern "C" void kernel_launch(void* const* d_in, const int* in_sizes, int n_in,
                              void* d_out, int out_size)
{
    (void)in_sizes; (void)n_in; (void)out_size;
    const float* x      = (const float*)d_in[0];
    const float* c4t    = (const float*)d_in[1];
    const float* c      = (const float*)d_in[2];
    const float* W_ada  = (const float*)d_in[3];
    const float* b_ada  = (const float*)d_in[4];
    const float* tn_w   = (const float*)d_in[5];
    const float* tn_b   = (const float*)d_in[6];
    const float* t_qkv  = (const float*)d_in[7];
    const float* t_k    = (const float*)d_in[8];
    const float* t_v    = (const float*)d_in[9];
    const float* t_out  = (const float*)d_in[10];
    const float* t_fc_w = (const float*)d_in[11];
    const float* t_fc_b = (const float*)d_in[12];
    const float* s_qkv  = (const float*)d_in[13];
    const float* s_k    = (const float*)d_in[14];
    const float* s_v    = (const float*)d_in[15];
    const float* s_out  = (const float*)d_in[16];
    const float* mlp_w1 = (const float*)d_in[17];
    const float* mlp_b1 = (const float*)d_in[18];
    const float* mlp_w2 = (const float*)d_in[19];
    const float* mlp_b2 = (const float*)d_in[20];
    const int*   f      = (const int*)d_in[21];
    float* out = (float*)d_out;

    float *px4, *pln, *pattn, *pbig, *pada;
    cudaGetSymbolAddress((void**)&px4,  g_x4);
    cudaGetSymbolAddress((void**)&pln,  g_ln);
    cudaGetSymbolAddress((void**)&pattn,g_attn);
    cudaGetSymbolAddress((void**)&pbig, g_big);
    cudaGetSymbolAddress((void**)&pada, g_ada);

    ada_kernel<<<dim3(ADAW / 128, BB), 128>>>(c4t, W_ada, b_ada);
    rope_kernel<<<1, TT * (DD / 2)>>>(f);
    ekv_kernel<<<dim3(BB * TT, 4), 256>>>(c, t_k, t_v, s_k, s_v);

    // temporal branch
    ln_kernel<<<ROWS, 256>>>(x, pln, px4, tn_w, tn_b, nullptr, 0, 0, 1e-5f, 1);
    tc_gemm_kernel<<<dim3(QKVW / 128, ROWS / 128), 256, TCG_SMEM>>>(
        pln, t_qkv, nullptr, nullptr, nullptr, pbig, MM, QKVW, 0, 0);
    attn_t_kernel<<<dim3(HH, NN, BB), 256>>>();
    tc_gemm_kernel<<<dim3(MM / 128, ROWS / 128), 256, TCG_SMEM>>>(
        pattn, t_out, nullptr, nullptr, nullptr, pln, MM, MM, 0, 1);
    tc_gemm_kernel<<<dim3(MM / 128, ROWS / 128), 256, TCG_SMEM>>>(
        pln, t_fc_w, t_fc_b, px4, nullptr, px4, MM, MM, 0, 0);

    // spatial branch
    ln_kernel<<<ROWS, 256>>>(px4, pln, nullptr, nullptr, nullptr, pada, 0, MM, 1e-6f, 0);
    tc_gemm_kernel<<<dim3(QKVW / 128, ROWS / 128), 256, TCG_SMEM>>>(
        pln, s_qkv, nullptr, nullptr, nullptr, pbig, MM, QKVW, 0, 0);
    attn_s_kernel<<<dim3(HH, TT, BB), 256>>>();
    tc_gemm_kernel<<<dim3(MM / 128, ROWS / 128), 256, TCG_SMEM>>>(
        pattn, s_out, nullptr, px4, pada + 2 * MM, px4, MM, MM, 0, 0);

    // MLP
    ln_kernel<<<ROWS, 256>>>(px4, pln, nullptr, nullptr, nullptr, pada, 3 * MM, 4 * MM, 1e-6f, 0);
    tc_gemm_kernel<<<dim3(MLPW / 128, ROWS / 128), 256, TCG_SMEM>>>(
        pln, mlp_w1, mlp_b1, nullptr, nullptr, pbig, MM, MLPW, 1, 0);
    tc_gemm_kernel<<<dim3(MM / 128, ROWS / 128), 256, TCG_SMEM>>>(
        pbig, mlp_w2, mlp_b2, px4, pada + 5 * MM, out, MLPW, MM, 0, 0);
}

// round 9
// speedup vs baseline: 2.5630x; 1.2532x over previous
#include <cuda_runtime.h>
#include <cuda_fp16.h>
#include <cstdint>

#define BB 2
#define TT 16
#define NN 256
#define MM 1152
#define HH 16
#define DD 72
#define ROWS 8192
#define ADAW 6912
#define QKVW 3456
#define MLPW 4608
#define SCALE 0.11785113019775793f

// ---------------- scratch -----------------------------------------------
__device__ float  g_x4[ROWS * MM];
__device__ __half g_lnh[ROWS * MM];
__device__ __half g_attnh[ROWS * MM];
__device__ __half g_bigh[(size_t)ROWS * MLPW];
__device__ float  g_ada[BB * ADAW];
__device__ float  g_tk[BB * TT * MM];
__device__ float  g_tv[BB * TT * MM];
__device__ float  g_sk[BB * TT * MM];
__device__ float  g_sv[BB * TT * MM];
__device__ float  g_ropec[TT * (DD / 2)];
__device__ float  g_ropes[TT * (DD / 2)];
// half transposed weights [N][K]
__device__ __half g_wh_tqkv[(size_t)QKVW * MM];
__device__ __half g_wh_tout[(size_t)MM * MM];
__device__ __half g_wh_tfc[(size_t)MM * MM];
__device__ __half g_wh_sqkv[(size_t)QKVW * MM];
__device__ __half g_wh_sout[(size_t)MM * MM];
__device__ __half g_wh_w1[(size_t)MLPW * MM];
__device__ __half g_wh_w2[(size_t)MM * MLPW];

// ---------------- helpers -------------------------------------------------
__device__ __forceinline__ void cpa16(void* s, const void* g) {
    uint32_t sa;
    asm("{ .reg .u64 t; cvta.to.shared.u64 t, %1; cvt.u32.u64 %0, t; }"
        : "=r"(sa) : "l"(s));
    asm volatile("cp.async.cg.shared.global [%0], [%1], 16;" :: "r"(sa), "l"(g));
}
__device__ __forceinline__ void mma16816(float* d, const uint32_t* a, const uint32_t* b) {
    asm volatile(
        "mma.sync.aligned.m16n8k16.row.col.f32.f16.f16.f32 "
        "{%0,%1,%2,%3},{%4,%5,%6,%7},{%8,%9},{%0,%1,%2,%3};"
        : "+f"(d[0]), "+f"(d[1]), "+f"(d[2]), "+f"(d[3])
        : "r"(a[0]), "r"(a[1]), "r"(a[2]), "r"(a[3]), "r"(b[0]), "r"(b[1]));
}

// ---------------- weight transpose+convert [K,N]f32 -> [N,K]h ------------
__global__ __launch_bounds__(256) void convw_kernel(
    const float* __restrict__ S, __half* __restrict__ D, int K, int N)
{
    __shared__ float t[32][33];
    int x = blockIdx.x * 32 + threadIdx.x;
    int y0 = blockIdx.y * 32;
#pragma unroll
    for (int j = threadIdx.y; j < 32; j += 8)
        t[j][threadIdx.x] = S[(size_t)(y0 + j) * N + x];
    __syncthreads();
    int x2 = y0 + threadIdx.x;
    int y2 = blockIdx.x * 32;
#pragma unroll
    for (int j = threadIdx.y; j < 32; j += 8)
        D[(size_t)(y2 + j) * K + x2] = __float2half(t[threadIdx.x][j]);
}

// ---------------- fp16 mma GEMM: CTA 128x128, warp 32x64, Kc=32 ----------
// smem halves, stride 40 (80B = 20 banks): frag loads conflict-free.
#define HSTR 40
#define TILE_H (128 * HSTR)            // halves per operand tile
#define STAGE_H (2 * TILE_H)           // A + B
__global__ __launch_bounds__(256) void tc_gemm_kernel(
    const __half* __restrict__ A, const __half* __restrict__ W,
    const float* __restrict__ bias, const float* __restrict__ addsrc,
    const float* __restrict__ gate,
    float* __restrict__ Cf, __half* __restrict__ Ch,
    int K, int Nc, int act, int permute)
{
    __shared__ __half smem[2 * STAGE_H];
    int tid = threadIdx.x, lane = tid & 31, wid = tid >> 5;
    int wm = wid & 3, wn = wid >> 2;
    int qrow = lane >> 2, qk = lane & 3;
    int blockCol = blockIdx.x * 128, blockRow = blockIdx.y * 128;
    int nc = K >> 5;

    float acc[2][8][4];
#pragma unroll
    for (int mt = 0; mt < 2; mt++)
#pragma unroll
        for (int nt = 0; nt < 8; nt++)
#pragma unroll
            for (int r = 0; r < 4; r++) acc[mt][nt][r] = 0.f;

    // cp.async plan: per chunk, A = 512 16B segs (row = a>>2, seg = a&3), B same.
    int a0 = tid, a1 = tid + 256;
    int ar0 = a0 >> 2, as0 = a0 & 3, ar1 = a1 >> 2, as1 = a1 & 3;
    const __half* Ab = A + (size_t)blockRow * K;
    const __half* Bb = W + (size_t)blockCol * K;

#define PREFETCH(chunk, stg) do {                                               \
    __half* As = smem + (stg) * STAGE_H;                                         \
    __half* Bs = As + TILE_H;                                                    \
    int k0 = (chunk) << 5;                                                       \
    cpa16(As + ar0 * HSTR + as0 * 8, Ab + (size_t)ar0 * K + k0 + as0 * 8);       \
    cpa16(As + ar1 * HSTR + as1 * 8, Ab + (size_t)ar1 * K + k0 + as1 * 8);       \
    cpa16(Bs + ar0 * HSTR + as0 * 8, Bb + (size_t)ar0 * K + k0 + as0 * 8);       \
    cpa16(Bs + ar1 * HSTR + as1 * 8, Bb + (size_t)ar1 * K + k0 + as1 * 8);       \
    asm volatile("cp.async.commit_group;" ::: "memory");                         \
} while (0)

    PREFETCH(0, 0);

#pragma unroll 1
    for (int i = 0; i < nc; i++) {
        if (i + 1 < nc) {
            PREFETCH(i + 1, (i + 1) & 1);
            asm volatile("cp.async.wait_group 1;" ::: "memory");
        } else {
            asm volatile("cp.async.wait_group 0;" ::: "memory");
        }
        __syncthreads();
        const __half* As = smem + (i & 1) * STAGE_H;
        const __half* Bs = As + TILE_H;
#pragma unroll
        for (int kk = 0; kk < 2; kk++) {
            int kb = kk * 16;
            uint32_t a[2][4], b[8][2];
#pragma unroll
            for (int mt = 0; mt < 2; mt++) {
                int m = wm * 32 + mt * 16 + qrow;
                a[mt][0] = *(const uint32_t*)&As[m * HSTR + kb + 2 * qk];
                a[mt][1] = *(const uint32_t*)&As[(m + 8) * HSTR + kb + 2 * qk];
                a[mt][2] = *(const uint32_t*)&As[m * HSTR + kb + 2 * qk + 8];
                a[mt][3] = *(const uint32_t*)&As[(m + 8) * HSTR + kb + 2 * qk + 8];
            }
#pragma unroll
            for (int nt = 0; nt < 8; nt++) {
                int n = wn * 64 + nt * 8 + qrow;
                b[nt][0] = *(const uint32_t*)&Bs[n * HSTR + kb + 2 * qk];
                b[nt][1] = *(const uint32_t*)&Bs[n * HSTR + kb + 2 * qk + 8];
            }
#pragma unroll
            for (int mt = 0; mt < 2; mt++)
#pragma unroll
                for (int nt = 0; nt < 8; nt++)
                    mma16816(acc[mt][nt], a[mt], b[nt]);
        }
        __syncthreads();
    }

    // epilogue: d0:(r,c) d1:(r,c+1) d2:(r+8,c) d3:(r+8,c+1)
#pragma unroll
    for (int mt = 0; mt < 2; mt++) {
#pragma unroll
        for (int half = 0; half < 2; half++) {
            int row = blockRow + wm * 32 + mt * 16 + qrow + half * 8;
            int bch = row >> 12;
            int orow = row;
            if (permute) {
                int rem = row & 4095;
                orow = ((bch << 4) + (rem & 15)) * NN + (rem >> 4);
            }
            float* crow = Cf ? Cf + (size_t)orow * Nc : nullptr;
            __half* hrow = Ch ? Ch + (size_t)orow * Nc : nullptr;
            const float* arow = addsrc ? addsrc + (size_t)orow * Nc : nullptr;
#pragma unroll
            for (int nt = 0; nt < 8; nt++) {
#pragma unroll
                for (int e = 0; e < 2; e++) {
                    int col = blockCol + wn * 64 + nt * 8 + 2 * qk + e;
                    float v = acc[mt][nt][half * 2 + e];
                    if (bias) v += bias[col];
                    if (act) {
                        float xg = v;
                        v = 0.5f * xg * (1.f + tanhf(0.7978845608028654f *
                                (xg + 0.044715f * xg * xg * xg)));
                    }
                    if (gate) v *= gate[bch * ADAW + col];
                    if (arow) v += arow[col];
                    if (crow) crow[col] = v;
                    if (hrow) hrow[col] = __float2half(v);
                }
            }
        }
    }
}

// ---------------- ada = silu(c4t) @ W_ada + b_ada -------------------------
__global__ __launch_bounds__(128) void ada_kernel(
    const float* __restrict__ c4t, const float* __restrict__ W,
    const float* __restrict__ bias)
{
    __shared__ float ss[MM];
    int b = blockIdx.y;
    for (int i = threadIdx.x; i < MM; i += 128) {
        float v = c4t[b * MM + i];
        ss[i] = v / (1.f + expf(-v));
    }
    __syncthreads();
    int col = blockIdx.x * 128 + threadIdx.x;
    float acc = bias[col];
    for (int k = 0; k < MM; k++)
        acc += ss[k] * W[(size_t)k * ADAW + col];
    g_ada[b * ADAW + col] = acc;
}

// ---------------- rope tables ---------------------------------------------
__global__ void rope_kernel(const int* __restrict__ f)
{
    int idx = threadIdx.x;
    if (idx < TT * (DD / 2)) {
        int t = idx / (DD / 2), i = idx % (DD / 2);
        float pos = (float)f[t];
        float freq = powf(10000.f, -((2.f * (float)i) / (float)DD));
        float a = pos * freq;
        g_ropec[idx] = cosf(a);
        g_ropes[idx] = sinf(a);
    }
}

// ---------------- extra-KV projections ------------------------------------
__global__ __launch_bounds__(256) void ekv_kernel(
    const float* __restrict__ c,
    const float* __restrict__ tk, const float* __restrict__ tv,
    const float* __restrict__ sk, const float* __restrict__ sv)
{
    __shared__ float cs[MM];
    int row = blockIdx.x;
    int which = blockIdx.y;
    const float* W = (which == 0) ? tk : (which == 1) ? tv : (which == 2) ? sk : sv;
    float* O = (which == 0) ? g_tk : (which == 1) ? g_tv : (which == 2) ? g_sk : g_sv;
    for (int i = threadIdx.x; i < MM; i += 256) cs[i] = c[(size_t)row * MM + i];
    __syncthreads();
    for (int col = threadIdx.x; col < MM; col += 256) {
        float acc = 0.f;
        for (int k = 0; k < MM; k++)
            acc += cs[k] * W[(size_t)k * MM + col];
        O[(size_t)row * MM + col] = acc;
    }
}

// ---------------- LayerNorm (half output) ----------------------------------
__global__ __launch_bounds__(256) void ln_kernel(
    const float* __restrict__ X, __half* __restrict__ out, float* __restrict__ copyDst,
    const float* __restrict__ w, const float* __restrict__ bvec,
    const float* __restrict__ ada, int shOff, int scOff, float eps, int permute)
{
    int row = blockIdx.x;
    const float* xr = X + (size_t)row * MM;
    float xv[5];
    float s = 0.f, sq = 0.f;
    int k = 0;
    for (int i = threadIdx.x; i < MM; i += 256, k++) {
        float v = xr[i];
        xv[k] = v;
        s += v; sq += v * v;
    }
    __shared__ float reds[8], redq[8], stats[2];
    for (int off = 16; off > 0; off >>= 1) {
        s  += __shfl_xor_sync(0xffffffffu, s,  off);
        sq += __shfl_xor_sync(0xffffffffu, sq, off);
    }
    int wid = threadIdx.x >> 5, lane = threadIdx.x & 31;
    if (lane == 0) { reds[wid] = s; redq[wid] = sq; }
    __syncthreads();
    if (threadIdx.x == 0) {
        float ts = 0.f, tq = 0.f;
        for (int i2 = 0; i2 < 8; i2++) { ts += reds[i2]; tq += redq[i2]; }
        float mean = ts * (1.f / MM);
        float var = tq * (1.f / MM) - mean * mean;
        stats[0] = mean;
        stats[1] = rsqrtf(var + eps);
    }
    __syncthreads();
    float mean = stats[0], rstd = stats[1];
    int b = row >> 12;
    int orow = row;
    if (permute) {
        int rem = row & 4095;
        int t = rem >> 8, n = rem & 255;
        orow = ((b << 8) + n) * TT + t;
    }
    k = 0;
    for (int i = threadIdx.x; i < MM; i += 256, k++) {
        float v = xv[k];
        float nv = (v - mean) * rstd;
        float y;
        if (ada) y = nv * (1.f + ada[b * ADAW + scOff + i]) + ada[b * ADAW + shOff + i];
        else     y = nv * w[i] + bvec[i];
        out[(size_t)orow * MM + i] = __float2half(y);
        if (copyDst) copyDst[(size_t)row * MM + i] = v;
    }
}

// ---------------- temporal attention (half qkv in, half out) ---------------
__global__ __launch_bounds__(256) void attn_t_kernel()
{
    __shared__ float qs[TT * DD];
    __shared__ float kks[2 * TT * DD];
    __shared__ float vvs[2 * TT * DD];
    __shared__ float scs[TT * 2 * TT];
    int h = blockIdx.x, n = blockIdx.y, b = blockIdx.z;
    const __half* base = g_bigh + (size_t)((b * NN + n) * TT) * QKVW + h * DD;

    for (int idx = threadIdx.x; idx < TT * (DD / 2); idx += 256) {
        int t = idx / (DD / 2), i = idx % (DD / 2);
        float cc = g_ropec[idx], ssn = g_ropes[idx];
        const __half* qr = base + (size_t)t * QKVW + 2 * i;
        float x0 = __half2float(qr[0]), x1 = __half2float(qr[1]);
        qs[t * DD + 2 * i]     = SCALE * (x0 * cc - x1 * ssn);
        qs[t * DD + 2 * i + 1] = SCALE * (x1 * cc + x0 * ssn);
        const __half* kr = qr + MM;
        x0 = __half2float(kr[0]); x1 = __half2float(kr[1]);
        kks[(TT + t) * DD + 2 * i]     = x0 * cc - x1 * ssn;
        kks[(TT + t) * DD + 2 * i + 1] = x1 * cc + x0 * ssn;
        const float* er = g_tk + (size_t)(b * TT + t) * MM + h * DD + 2 * i;
        x0 = er[0]; x1 = er[1];
        kks[t * DD + 2 * i]     = x0 * cc - x1 * ssn;
        kks[t * DD + 2 * i + 1] = x1 * cc + x0 * ssn;
    }
    for (int idx = threadIdx.x; idx < TT * DD; idx += 256) {
        int t = idx / DD, d = idx % DD;
        vvs[(TT + t) * DD + d] = __half2float(base[(size_t)t * QKVW + 2 * MM + d]);
        vvs[t * DD + d] = g_tv[(size_t)(b * TT + t) * MM + h * DD + d];
    }
    __syncthreads();

    for (int idx = threadIdx.x; idx < TT * 2 * TT; idx += 256) {
        int t = idx / (2 * TT), j = idx % (2 * TT);
        float acc = 0.f;
#pragma unroll
        for (int d = 0; d < DD; d++) acc += qs[t * DD + d] * kks[j * DD + d];
        scs[idx] = acc;
    }
    __syncthreads();

    if (threadIdx.x < TT) {
        int t = threadIdx.x;
        float m = -1e30f;
        for (int j = 0; j < 2 * TT; j++) m = fmaxf(m, scs[t * 2 * TT + j]);
        float sum = 0.f;
        for (int j = 0; j < 2 * TT; j++) {
            float p = __expf(scs[t * 2 * TT + j] - m);
            scs[t * 2 * TT + j] = p;
            sum += p;
        }
        float inv = 1.f / sum;
        for (int j = 0; j < 2 * TT; j++) scs[t * 2 * TT + j] *= inv;
    }
    __syncthreads();

    for (int idx = threadIdx.x; idx < TT * DD; idx += 256) {
        int t = idx / DD, d = idx % DD;
        float acc = 0.f;
#pragma unroll
        for (int j = 0; j < 2 * TT; j++) acc += scs[t * 2 * TT + j] * vvs[j * DD + d];
        g_attnh[(size_t)((b * NN + n) * TT + t) * MM + h * DD + d] = __float2half(acc);
    }
}

// ---------------- spatial attention: online softmax, smem KV tiles ---------
#define SKV 64
__global__ __launch_bounds__(256) void attn_s_kernel()
{
    __shared__ __half kt[SKV * DD];
    __shared__ __half vt[SKV * DD];
    int h = blockIdx.x, t = blockIdx.y, b = blockIdx.z;
    int n = threadIdx.x;
    const __half* base = g_bigh + (size_t)((b * TT + t) * NN) * QKVW;

    uint32_t q2[DD / 2];
    {
        const uint32_t* qr = (const uint32_t*)(base + (size_t)n * QKVW + h * DD);
#pragma unroll
        for (int i = 0; i < DD / 2; i++) q2[i] = qr[i];
    }
    float acc[DD];
#pragma unroll
    for (int d = 0; d < DD; d++) acc[d] = 0.f;
    float mcur = -1e30f, lsum = 0.f;

    for (int tile = 0; tile < (NN + 1 + SKV - 1) / SKV; tile++) {
        int j0 = tile * SKV;
        int jcount = (NN + 1) - j0;
        if (jcount > SKV) jcount = SKV;
        __syncthreads();
        for (int idx = threadIdx.x; idx < jcount * (DD / 2); idx += 256) {
            int jj = idx / (DD / 2), dp = idx % (DD / 2);
            int j = j0 + jj;
            __half2 kv2, vv2;
            if (j == 0) {
                const float* kf = g_sk + (size_t)(b * TT + t) * MM + h * DD + 2 * dp;
                const float* vf = g_sv + (size_t)(b * TT + t) * MM + h * DD + 2 * dp;
                kv2 = __floats2half2_rn(kf[0], kf[1]);
                vv2 = __floats2half2_rn(vf[0], vf[1]);
            } else {
                const __half* krow = base + (size_t)(j - 1) * QKVW + MM + h * DD;
                const __half* vrow = base + (size_t)(j - 1) * QKVW + 2 * MM + h * DD;
                kv2 = *(const __half2*)(krow + 2 * dp);
                vv2 = *(const __half2*)(vrow + 2 * dp);
            }
            *(__half2*)&kt[jj * DD + 2 * dp] = kv2;
            *(__half2*)&vt[jj * DD + 2 * dp] = vv2;
        }
        __syncthreads();

        for (int jj = 0; jj < jcount; jj++) {
            float s = 0.f;
#pragma unroll
            for (int i = 0; i < DD / 2; i++) {
                float2 kp = __half22float2(*(const __half2*)&kt[jj * DD + 2 * i]);
                float2 qp = __half22float2(*(const __half2*)&q2[i]);
                s += qp.x * kp.x + qp.y * kp.y;
            }
            s *= SCALE;
            if (s > mcur) {
                float c = __expf(mcur - s);
                lsum *= c;
#pragma unroll
                for (int d = 0; d < DD; d++) acc[d] *= c;
                mcur = s;
            }
            float p = __expf(s - mcur);
            lsum += p;
#pragma unroll
            for (int i = 0; i < DD / 2; i++) {
                float2 vp = __half22float2(*(const __half2*)&vt[jj * DD + 2 * i]);
                acc[2 * i]     += p * vp.x;
                acc[2 * i + 1] += p * vp.y;
            }
        }
    }
    float inv = 1.f / lsum;
    __half* orow = g_attnh + (size_t)((b * TT + t) * NN + n) * MM + h * DD;
#pragma unroll
    for (int d = 0; d < DD; d++) orow[d] = __float2half(acc[d] * inv);
}

// ---------------- launch ----------------------------------------------------
extern "C" void kernel_launch(void* const* d_in, const int* in_sizes, int n_in,
                              void* d_out, int out_size)
{
    (void)in_sizes; (void)n_in; (void)out_size;
    const float* x      = (const float*)d_in[0];
    const float* c4t    = (const float*)d_in[1];
    const float* c      = (const float*)d_in[2];
    const float* W_ada  = (const float*)d_in[3];
    const float* b_ada  = (const float*)d_in[4];
    const float* tn_w   = (const float*)d_in[5];
    const float* tn_b   = (const float*)d_in[6];
    const float* t_qkv  = (const float*)d_in[7];
    const float* t_k    = (const float*)d_in[8];
    const float* t_v    = (const float*)d_in[9];
    const float* t_out  = (const float*)d_in[10];
    const float* t_fc_w = (const float*)d_in[11];
    const float* t_fc_b = (const float*)d_in[12];
    const float* s_qkv  = (const float*)d_in[13];
    const float* s_k    = (const float*)d_in[14];
    const float* s_v    = (const float*)d_in[15];
    const float* s_out  = (const float*)d_in[16];
    const float* mlp_w1 = (const float*)d_in[17];
    const float* mlp_b1 = (const float*)d_in[18];
    const float* mlp_w2 = (const float*)d_in[19];
    const float* mlp_b2 = (const float*)d_in[20];
    const int*   f      = (const int*)d_in[21];
    float* out = (float*)d_out;

    float *px4, *pada;
    __half *plnh, *pattnh, *pbigh;
    __half *wtq, *wto, *wtf, *wsq, *wso, *ww1, *ww2;
    cudaGetSymbolAddress((void**)&px4,   g_x4);
    cudaGetSymbolAddress((void**)&pada,  g_ada);
    cudaGetSymbolAddress((void**)&plnh,  g_lnh);
    cudaGetSymbolAddress((void**)&pattnh,g_attnh);
    cudaGetSymbolAddress((void**)&pbigh, g_bigh);
    cudaGetSymbolAddress((void**)&wtq,   g_wh_tqkv);
    cudaGetSymbolAddress((void**)&wto,   g_wh_tout);
    cudaGetSymbolAddress((void**)&wtf,   g_wh_tfc);
    cudaGetSymbolAddress((void**)&wsq,   g_wh_sqkv);
    cudaGetSymbolAddress((void**)&wso,   g_wh_sout);
    cudaGetSymbolAddress((void**)&ww1,   g_wh_w1);
    cudaGetSymbolAddress((void**)&ww2,   g_wh_w2);

    // weight convert+transpose
    convw_kernel<<<dim3(QKVW / 32, MM / 32), dim3(32, 8)>>>(t_qkv, wtq, MM, QKVW);
    convw_kernel<<<dim3(MM / 32, MM / 32), dim3(32, 8)>>>(t_out, wto, MM, MM);
    convw_kernel<<<dim3(MM / 32, MM / 32), dim3(32, 8)>>>(t_fc_w, wtf, MM, MM);
    convw_kernel<<<dim3(QKVW / 32, MM / 32), dim3(32, 8)>>>(s_qkv, wsq, MM, QKVW);
    convw_kernel<<<dim3(MM / 32, MM / 32), dim3(32, 8)>>>(s_out, wso, MM, MM);
    convw_kernel<<<dim3(MLPW / 32, MM / 32), dim3(32, 8)>>>(mlp_w1, ww1, MM, MLPW);
    convw_kernel<<<dim3(MM / 32, MLPW / 32), dim3(32, 8)>>>(mlp_w2, ww2, MLPW, MM);

    ada_kernel<<<dim3(ADAW / 128, BB), 128>>>(c4t, W_ada, b_ada);
    rope_kernel<<<1, TT * (DD / 2)>>>(f);
    ekv_kernel<<<dim3(BB * TT, 4), 256>>>(c, t_k, t_v, s_k, s_v);

    // temporal branch
    ln_kernel<<<ROWS, 256>>>(x, plnh, px4, tn_w, tn_b, nullptr, 0, 0, 1e-5f, 1);
    tc_gemm_kernel<<<dim3(QKVW / 128, ROWS / 128), 256>>>(
        plnh, wtq, nullptr, nullptr, nullptr, nullptr, pbigh, MM, QKVW, 0, 0);
    attn_t_kernel<<<dim3(HH, NN, BB), 256>>>();
    tc_gemm_kernel<<<dim3(MM / 128, ROWS / 128), 256>>>(
        pattnh, wto, nullptr, nullptr, nullptr, nullptr, plnh, MM, MM, 0, 1);
    tc_gemm_kernel<<<dim3(MM / 128, ROWS / 128), 256>>>(
        plnh, wtf, t_fc_b, px4, nullptr, px4, nullptr, MM, MM, 0, 0);

    // spatial branch
    ln_kernel<<<ROWS, 256>>>(px4, plnh, nullptr, nullptr, nullptr, pada, 0, MM, 1e-6f, 0);
    tc_gemm_kernel<<<dim3(QKVW / 128, ROWS / 128), 256>>>(
        plnh, wsq, nullptr, nullptr, nullptr, nullptr, pbigh, MM, QKVW, 0, 0);
    attn_s_kernel<<<dim3(HH, TT, BB), 256>>>();
    tc_gemm_kernel<<<dim3(MM / 128, ROWS / 128), 256>>>(
        pattnh, wso, nullptr, px4, pada + 2 * MM, px4, nullptr, MM, MM, 0, 0);

    // MLP
    ln_kernel<<<ROWS, 256>>>(px4, plnh, nullptr, nullptr, nullptr, pada, 3 * MM, 4 * MM, 1e-6f, 0);
    tc_gemm_kernel<<<dim3(MLPW / 128, ROWS / 128), 256>>>(
        plnh, ww1, mlp_b1, nullptr, nullptr, nullptr, pbigh, MM, MLPW, 1, 0);
    tc_gemm_kernel<<<dim3(MM / 128, ROWS / 128), 256>>>(
        pbigh, ww2, mlp_b2, px4, pada + 5 * MM, out, nullptr, MLPW, MM, 0, 0);
}

// round 12
// speedup vs baseline: 4.1394x; 1.6150x over previous
#include <cuda_runtime.h>
#include <cuda_fp16.h>
#include <cstdint>

#define BB 2
#define TT 16
#define NN 256
#define MM 1152
#define HH 16
#define DD 72
#define ROWS 8192
#define ADAW 6912
#define QKVW 3456
#define MLPW 4608
#define SCALE 0.11785113019775793f

// ---------------- scratch -----------------------------------------------
__device__ float  g_x4[ROWS * MM];
__device__ __half g_lnh[ROWS * MM];
__device__ __half g_attnh[ROWS * MM];
__device__ __half g_bigh[(size_t)ROWS * MLPW];
__device__ float  g_ada[BB * ADAW];
__device__ float  g_tk[BB * TT * MM];
__device__ float  g_tv[BB * TT * MM];
__device__ float  g_sk[BB * TT * MM];
__device__ float  g_sv[BB * TT * MM];
__device__ float  g_ropec[TT * (DD / 2)];
__device__ float  g_ropes[TT * (DD / 2)];
// half transposed weights [N][K]
__device__ __half g_wh_tqkv[(size_t)QKVW * MM];
__device__ __half g_wh_tout[(size_t)MM * MM];
__device__ __half g_wh_tfc[(size_t)MM * MM];
__device__ __half g_wh_sqkv[(size_t)QKVW * MM];
__device__ __half g_wh_sout[(size_t)MM * MM];
__device__ __half g_wh_w1[(size_t)MLPW * MM];
__device__ __half g_wh_w2[(size_t)MM * MLPW];

// ---------------- helpers -------------------------------------------------
__device__ __forceinline__ uint32_t s2u(const void* p) {
    uint32_t a;
    asm("{ .reg .u64 t; cvta.to.shared.u64 t, %1; cvt.u32.u64 %0, t; }"
        : "=r"(a) : "l"(p));
    return a;
}
__device__ __forceinline__ void cpa16(void* s, const void* g) {
    asm volatile("cp.async.cg.shared.global [%0], [%1], 16;" :: "r"(s2u(s)), "l"(g));
}
__device__ __forceinline__ void ldsm4(uint32_t* r, const void* p) {
    asm volatile("ldmatrix.sync.aligned.m8n8.x4.shared.b16 {%0,%1,%2,%3}, [%4];"
        : "=r"(r[0]), "=r"(r[1]), "=r"(r[2]), "=r"(r[3]) : "r"(s2u(p)));
}
__device__ __forceinline__ void mma16816(float* d, const uint32_t* a, const uint32_t* b) {
    asm volatile(
        "mma.sync.aligned.m16n8k16.row.col.f32.f16.f16.f32 "
        "{%0,%1,%2,%3},{%4,%5,%6,%7},{%8,%9},{%0,%1,%2,%3};"
        : "+f"(d[0]), "+f"(d[1]), "+f"(d[2]), "+f"(d[3])
        : "r"(a[0]), "r"(a[1]), "r"(a[2]), "r"(a[3]), "r"(b[0]), "r"(b[1]));
}

// ---------------- weight transpose+convert [K,N]f32 -> [N,K]h ------------
__global__ __launch_bounds__(256) void convw_kernel(
    const float* __restrict__ S, __half* __restrict__ D, int K, int N)
{
    __shared__ float t[32][33];
    int x = blockIdx.x * 32 + threadIdx.x;
    int y0 = blockIdx.y * 32;
#pragma unroll
    for (int j = threadIdx.y; j < 32; j += 8)
        t[j][threadIdx.x] = S[(size_t)(y0 + j) * N + x];
    __syncthreads();
    int x2 = y0 + threadIdx.x;
    int y2 = blockIdx.x * 32;
#pragma unroll
    for (int j = threadIdx.y; j < 32; j += 8)
        D[(size_t)(y2 + j) * K + x2] = __float2half(t[threadIdx.x][j]);
}

// ---------------- fp16 mma GEMM: CTA 128x128, warp 32x64, Kc=32 ----------
// 3-stage cp.async ring (wait -> barrier -> prefetch -> compute), ldmatrix,
// 2 CTAs/SM. smem row stride 40 halves (80B): ldsm rows partition banks.
#define HSTR 40
#define TILE_H (128 * HSTR)            // halves per operand tile
#define STAGE_H (2 * TILE_H)           // A + B
#define TCG_SMEM (3 * STAGE_H * 2)     // bytes
__global__ __launch_bounds__(256, 2) void tc_gemm_kernel(
    const __half* __restrict__ A, const __half* __restrict__ W,
    const float* __restrict__ bias, const float* __restrict__ addsrc,
    const float* __restrict__ gate,
    float* __restrict__ Cf, __half* __restrict__ Ch,
    int K, int Nc, int act, int permute)
{
    extern __shared__ __half smem[];
    int tid = threadIdx.x, lane = tid & 31, wid = tid >> 5;
    int wm = wid & 3, wn = wid >> 2;
    int qrow = lane >> 2, qk = lane & 3;
    int blockCol = blockIdx.x * 128, blockRow = blockIdx.y * 128;
    int nc = K >> 5;

    float acc[2][8][4];
#pragma unroll
    for (int mt = 0; mt < 2; mt++)
#pragma unroll
        for (int nt = 0; nt < 8; nt++)
#pragma unroll
            for (int r = 0; r < 4; r++) acc[mt][nt][r] = 0.f;

    // cp.async plan: per chunk, each operand = 512 16B segs; row=seg>>2, s=seg&3
    int a0 = tid, a1 = tid + 256;
    int ar0 = a0 >> 2, as0 = a0 & 3, ar1 = a1 >> 2, as1 = a1 & 3;
    const __half* Ab = A + (size_t)blockRow * K;
    const __half* Bb = W + (size_t)blockCol * K;

    // ldmatrix addresses (half offsets within tile)
    int amrow = wm * 32 + (lane & 15);
    int akoff = (lane >> 4) << 3;
    int bnrow = wn * 64 + (lane & 7) + ((lane >> 4) << 3);
    int bkoff = ((lane >> 3) & 1) << 3;

#define PREFETCH(chunk, stg_) do {                                              \
    __half* As_ = smem + (stg_) * STAGE_H;                                       \
    __half* Bs_ = As_ + TILE_H;                                                  \
    int k0 = (chunk) << 5;                                                       \
    cpa16(As_ + ar0 * HSTR + as0 * 8, Ab + (size_t)ar0 * K + k0 + as0 * 8);      \
    cpa16(As_ + ar1 * HSTR + as1 * 8, Ab + (size_t)ar1 * K + k0 + as1 * 8);      \
    cpa16(Bs_ + ar0 * HSTR + as0 * 8, Bb + (size_t)ar0 * K + k0 + as0 * 8);      \
    cpa16(Bs_ + ar1 * HSTR + as1 * 8, Bb + (size_t)ar1 * K + k0 + as1 * 8);      \
    asm volatile("cp.async.commit_group;" ::: "memory");                         \
} while (0)

    PREFETCH(0, 0);
    PREFETCH(1, 1);

    int stg = 0;
#pragma unroll 1
    for (int i = 0; i < nc; i++) {
        // my copies for chunk i done:
        if (i + 1 < nc) asm volatile("cp.async.wait_group 1;" ::: "memory");
        else            asm volatile("cp.async.wait_group 0;" ::: "memory");
        // ALL threads' copies for chunk i done; all reads of stage (i-1) done:
        __syncthreads();
        if (i + 2 < nc)
            PREFETCH(i + 2, (stg + 2 >= 3) ? stg - 1 : stg + 2);  // = stage (i-1)%3
        const __half* As = smem + stg * STAGE_H;
        const __half* Bs = As + TILE_H;
#pragma unroll
        for (int kk = 0; kk < 2; kk++) {
            int kb = kk * 16;
            uint32_t a[2][4], b[4][4];
            ldsm4(a[0], As + amrow * HSTR + kb + akoff);
            ldsm4(a[1], As + (amrow + 16) * HSTR + kb + akoff);
#pragma unroll
            for (int ntp = 0; ntp < 4; ntp++)
                ldsm4(b[ntp], Bs + (bnrow + ntp * 16) * HSTR + kb + bkoff);
#pragma unroll
            for (int mt = 0; mt < 2; mt++)
#pragma unroll
                for (int ntp = 0; ntp < 4; ntp++) {
                    mma16816(acc[mt][2 * ntp],     a[mt], &b[ntp][0]);
                    mma16816(acc[mt][2 * ntp + 1], a[mt], &b[ntp][2]);
                }
        }
        stg = (stg + 1 >= 3) ? 0 : stg + 1;
    }

    // epilogue: d0:(r,c) d1:(r,c+1) d2:(r+8,c) d3:(r+8,c+1)
#pragma unroll
    for (int mt = 0; mt < 2; mt++) {
#pragma unroll
        for (int half = 0; half < 2; half++) {
            int row = blockRow + wm * 32 + mt * 16 + qrow + half * 8;
            int bch = row >> 12;
            int orow = row;
            if (permute) {
                int rem = row & 4095;
                orow = ((bch << 4) + (rem & 15)) * NN + (rem >> 4);
            }
            float* crow = Cf ? Cf + (size_t)orow * Nc : nullptr;
            __half* hrow = Ch ? Ch + (size_t)orow * Nc : nullptr;
            const float* arow = addsrc ? addsrc + (size_t)orow * Nc : nullptr;
#pragma unroll
            for (int nt = 0; nt < 8; nt++) {
#pragma unroll
                for (int e = 0; e < 2; e++) {
                    int col = blockCol + wn * 64 + nt * 8 + 2 * qk + e;
                    float v = acc[mt][nt][half * 2 + e];
                    if (bias) v += bias[col];
                    if (act) {
                        float xg = v;
                        v = 0.5f * xg * (1.f + tanhf(0.7978845608028654f *
                                (xg + 0.044715f * xg * xg * xg)));
                    }
                    if (gate) v *= gate[bch * ADAW + col];
                    if (arow) v += arow[col];
                    if (crow) crow[col] = v;
                    if (hrow) hrow[col] = __float2half(v);
                }
            }
        }
    }
}

// ---------------- ada = silu(c4t) @ W_ada + b_ada -------------------------
__global__ __launch_bounds__(128) void ada_kernel(
    const float* __restrict__ c4t, const float* __restrict__ W,
    const float* __restrict__ bias)
{
    __shared__ float ss[MM];
    int b = blockIdx.y;
    for (int i = threadIdx.x; i < MM; i += 128) {
        float v = c4t[b * MM + i];
        ss[i] = v / (1.f + expf(-v));
    }
    __syncthreads();
    int col = blockIdx.x * 128 + threadIdx.x;
    float acc = bias[col];
    for (int k = 0; k < MM; k++)
        acc += ss[k] * W[(size_t)k * ADAW + col];
    g_ada[b * ADAW + col] = acc;
}

// ---------------- rope tables ---------------------------------------------
__global__ void rope_kernel(const int* __restrict__ f)
{
    int idx = threadIdx.x;
    if (idx < TT * (DD / 2)) {
        int t = idx / (DD / 2), i = idx % (DD / 2);
        float pos = (float)f[t];
        float freq = powf(10000.f, -((2.f * (float)i) / (float)DD));
        float a = pos * freq;
        g_ropec[idx] = cosf(a);
        g_ropes[idx] = sinf(a);
    }
}

// ---------------- extra-KV projections ------------------------------------
__global__ __launch_bounds__(256) void ekv_kernel(
    const float* __restrict__ c,
    const float* __restrict__ tk, const float* __restrict__ tv,
    const float* __restrict__ sk, const float* __restrict__ sv)
{
    __shared__ float cs[MM];
    int row = blockIdx.x;
    int which = blockIdx.y;
    const float* W = (which == 0) ? tk : (which == 1) ? tv : (which == 2) ? sk : sv;
    float* O = (which == 0) ? g_tk : (which == 1) ? g_tv : (which == 2) ? g_sk : g_sv;
    for (int i = threadIdx.x; i < MM; i += 256) cs[i] = c[(size_t)row * MM + i];
    __syncthreads();
    for (int col = threadIdx.x; col < MM; col += 256) {
        float acc = 0.f;
        for (int k = 0; k < MM; k++)
            acc += cs[k] * W[(size_t)k * MM + col];
        O[(size_t)row * MM + col] = acc;
    }
}

// ---------------- LayerNorm (half output) ----------------------------------
__global__ __launch_bounds__(256) void ln_kernel(
    const float* __restrict__ X, __half* __restrict__ out, float* __restrict__ copyDst,
    const float* __restrict__ w, const float* __restrict__ bvec,
    const float* __restrict__ ada, int shOff, int scOff, float eps, int permute)
{
    int row = blockIdx.x;
    const float* xr = X + (size_t)row * MM;
    float xv[5];
    float s = 0.f, sq = 0.f;
    int k = 0;
    for (int i = threadIdx.x; i < MM; i += 256, k++) {
        float v = xr[i];
        xv[k] = v;
        s += v; sq += v * v;
    }
    __shared__ float reds[8], redq[8], stats[2];
    for (int off = 16; off > 0; off >>= 1) {
        s  += __shfl_xor_sync(0xffffffffu, s,  off);
        sq += __shfl_xor_sync(0xffffffffu, sq, off);
    }
    int wid = threadIdx.x >> 5, lane = threadIdx.x & 31;
    if (lane == 0) { reds[wid] = s; redq[wid] = sq; }
    __syncthreads();
    if (threadIdx.x == 0) {
        float ts = 0.f, tq = 0.f;
        for (int i2 = 0; i2 < 8; i2++) { ts += reds[i2]; tq += redq[i2]; }
        float mean = ts * (1.f / MM);
        float var = tq * (1.f / MM) - mean * mean;
        stats[0] = mean;
        stats[1] = rsqrtf(var + eps);
    }
    __syncthreads();
    float mean = stats[0], rstd = stats[1];
    int b = row >> 12;
    int orow = row;
    if (permute) {
        int rem = row & 4095;
        int t = rem >> 8, n = rem & 255;
        orow = ((b << 8) + n) * TT + t;
    }
    k = 0;
    for (int i = threadIdx.x; i < MM; i += 256, k++) {
        float v = xv[k];
        float nv = (v - mean) * rstd;
        float y;
        if (ada) y = nv * (1.f + ada[b * ADAW + scOff + i]) + ada[b * ADAW + shOff + i];
        else     y = nv * w[i] + bvec[i];
        out[(size_t)orow * MM + i] = __float2half(y);
        if (copyDst) copyDst[(size_t)row * MM + i] = v;
    }
}

// ---------------- temporal attention (half qkv in, half out) ---------------
__global__ __launch_bounds__(256) void attn_t_kernel()
{
    __shared__ float qs[TT * DD];
    __shared__ float kks[2 * TT * DD];
    __shared__ float vvs[2 * TT * DD];
    __shared__ float scs[TT * 2 * TT];
    int h = blockIdx.x, n = blockIdx.y, b = blockIdx.z;
    const __half* base = g_bigh + (size_t)((b * NN + n) * TT) * QKVW + h * DD;

    for (int idx = threadIdx.x; idx < TT * (DD / 2); idx += 256) {
        int t = idx / (DD / 2), i = idx % (DD / 2);
        float cc = g_ropec[idx], ssn = g_ropes[idx];
        const __half* qr = base + (size_t)t * QKVW + 2 * i;
        float x0 = __half2float(qr[0]), x1 = __half2float(qr[1]);
        qs[t * DD + 2 * i]     = SCALE * (x0 * cc - x1 * ssn);
        qs[t * DD + 2 * i + 1] = SCALE * (x1 * cc + x0 * ssn);
        const __half* kr = qr + MM;
        x0 = __half2float(kr[0]); x1 = __half2float(kr[1]);
        kks[(TT + t) * DD + 2 * i]     = x0 * cc - x1 * ssn;
        kks[(TT + t) * DD + 2 * i + 1] = x1 * cc + x0 * ssn;
        const float* er = g_tk + (size_t)(b * TT + t) * MM + h * DD + 2 * i;
        x0 = er[0]; x1 = er[1];
        kks[t * DD + 2 * i]     = x0 * cc - x1 * ssn;
        kks[t * DD + 2 * i + 1] = x1 * cc + x0 * ssn;
    }
    for (int idx = threadIdx.x; idx < TT * DD; idx += 256) {
        int t = idx / DD, d = idx % DD;
        vvs[(TT + t) * DD + d] = __half2float(base[(size_t)t * QKVW + 2 * MM + d]);
        vvs[t * DD + d] = g_tv[(size_t)(b * TT + t) * MM + h * DD + d];
    }
    __syncthreads();

    for (int idx = threadIdx.x; idx < TT * 2 * TT; idx += 256) {
        int t = idx / (2 * TT), j = idx % (2 * TT);
        float acc = 0.f;
#pragma unroll
        for (int d = 0; d < DD; d++) acc += qs[t * DD + d] * kks[j * DD + d];
        scs[idx] = acc;
    }
    __syncthreads();

    if (threadIdx.x < TT) {
        int t = threadIdx.x;
        float m = -1e30f;
        for (int j = 0; j < 2 * TT; j++) m = fmaxf(m, scs[t * 2 * TT + j]);
        float sum = 0.f;
        for (int j = 0; j < 2 * TT; j++) {
            float p = __expf(scs[t * 2 * TT + j] - m);
            scs[t * 2 * TT + j] = p;
            sum += p;
        }
        float inv = 1.f / sum;
        for (int j = 0; j < 2 * TT; j++) scs[t * 2 * TT + j] *= inv;
    }
    __syncthreads();

    for (int idx = threadIdx.x; idx < TT * DD; idx += 256) {
        int t = idx / DD, d = idx % DD;
        float acc = 0.f;
#pragma unroll
        for (int j = 0; j < 2 * TT; j++) acc += scs[t * 2 * TT + j] * vvs[j * DD + d];
        g_attnh[(size_t)((b * NN + n) * TT + t) * MM + h * DD + d] = __float2half(acc);
    }
}

// ---------------- spatial attention: online softmax, smem KV tiles ---------
#define SKV 64
__global__ __launch_bounds__(256) void attn_s_kernel()
{
    __shared__ __half kt[SKV * DD];
    __shared__ __half vt[SKV * DD];
    int h = blockIdx.x, t = blockIdx.y, b = blockIdx.z;
    int n = threadIdx.x;
    const __half* base = g_bigh + (size_t)((b * TT + t) * NN) * QKVW;

    uint32_t q2[DD / 2];
    {
        const uint32_t* qr = (const uint32_t*)(base + (size_t)n * QKVW + h * DD);
#pragma unroll
        for (int i = 0; i < DD / 2; i++) q2[i] = qr[i];
    }
    float acc[DD];
#pragma unroll
    for (int d = 0; d < DD; d++) acc[d] = 0.f;
    float mcur = -1e30f, lsum = 0.f;

    for (int tile = 0; tile < (NN + 1 + SKV - 1) / SKV; tile++) {
        int j0 = tile * SKV;
        int jcount = (NN + 1) - j0;
        if (jcount > SKV) jcount = SKV;
        __syncthreads();
        for (int idx = threadIdx.x; idx < jcount * (DD / 2); idx += 256) {
            int jj = idx / (DD / 2), dp = idx % (DD / 2);
            int j = j0 + jj;
            __half2 kv2, vv2;
            if (j == 0) {
                const float* kf = g_sk + (size_t)(b * TT + t) * MM + h * DD + 2 * dp;
                const float* vf = g_sv + (size_t)(b * TT + t) * MM + h * DD + 2 * dp;
                kv2 = __floats2half2_rn(kf[0], kf[1]);
                vv2 = __floats2half2_rn(vf[0], vf[1]);
            } else {
                const __half* krow = base + (size_t)(j - 1) * QKVW + MM + h * DD;
                const __half* vrow = base + (size_t)(j - 1) * QKVW + 2 * MM + h * DD;
                kv2 = *(const __half2*)(krow + 2 * dp);
                vv2 = *(const __half2*)(vrow + 2 * dp);
            }
            *(__half2*)&kt[jj * DD + 2 * dp] = kv2;
            *(__half2*)&vt[jj * DD + 2 * dp] = vv2;
        }
        __syncthreads();

        for (int jj = 0; jj < jcount; jj++) {
            float s = 0.f;
#pragma unroll
            for (int i = 0; i < DD / 2; i++) {
                float2 kp = __half22float2(*(const __half2*)&kt[jj * DD + 2 * i]);
                float2 qp = __half22float2(*(const __half2*)&q2[i]);
                s += qp.x * kp.x + qp.y * kp.y;
            }
            s *= SCALE;
            if (s > mcur) {
                float c = __expf(mcur - s);
                lsum *= c;
#pragma unroll
                for (int d = 0; d < DD; d++) acc[d] *= c;
                mcur = s;
            }
            float p = __expf(s - mcur);
            lsum += p;
#pragma unroll
            for (int i = 0; i < DD / 2; i++) {
                float2 vp = __half22float2(*(const __half2*)&vt[jj * DD + 2 * i]);
                acc[2 * i]     += p * vp.x;
                acc[2 * i + 1] += p * vp.y;
            }
        }
    }
    float inv = 1.f / lsum;
    __half* orow = g_attnh + (size_t)((b * TT + t) * NN + n) * MM + h * DD;
#pragma unroll
    for (int d = 0; d < DD; d++) orow[d] = __float2half(acc[d] * inv);
}

// ---------------- launch ----------------------------------------------------
extern "C" void kernel_launch(void* const* d_in, const int* in_sizes, int n_in,
                              void* d_out, int out_size)
{
    (void)in_sizes; (void)n_in; (void)out_size;
    const float* x      = (const float*)d_in[0];
    const float* c4t    = (const float*)d_in[1];
    const float* c      = (const float*)d_in[2];
    const float* W_ada  = (const float*)d_in[3];
    const float* b_ada  = (const float*)d_in[4];
    const float* tn_w   = (const float*)d_in[5];
    const float* tn_b   = (const float*)d_in[6];
    const float* t_qkv  = (const float*)d_in[7];
    const float* t_k    = (const float*)d_in[8];
    const float* t_v    = (const float*)d_in[9];
    const float* t_out  = (const float*)d_in[10];
    const float* t_fc_w = (const float*)d_in[11];
    const float* t_fc_b = (const float*)d_in[12];
    const float* s_qkv  = (const float*)d_in[13];
    const float* s_k    = (const float*)d_in[14];
    const float* s_v    = (const float*)d_in[15];
    const float* s_out  = (const float*)d_in[16];
    const float* mlp_w1 = (const float*)d_in[17];
    const float* mlp_b1 = (const float*)d_in[18];
    const float* mlp_w2 = (const float*)d_in[19];
    const float* mlp_b2 = (const float*)d_in[20];
    const int*   f      = (const int*)d_in[21];
    float* out = (float*)d_out;

    float *px4, *pada;
    __half *plnh, *pattnh, *pbigh;
    __half *wtq, *wto, *wtf, *wsq, *wso, *ww1, *ww2;
    cudaGetSymbolAddress((void**)&px4,   g_x4);
    cudaGetSymbolAddress((void**)&pada,  g_ada);
    cudaGetSymbolAddress((void**)&plnh,  g_lnh);
    cudaGetSymbolAddress((void**)&pattnh,g_attnh);
    cudaGetSymbolAddress((void**)&pbigh, g_bigh);
    cudaGetSymbolAddress((void**)&wtq,   g_wh_tqkv);
    cudaGetSymbolAddress((void**)&wto,   g_wh_tout);
    cudaGetSymbolAddress((void**)&wtf,   g_wh_tfc);
    cudaGetSymbolAddress((void**)&wsq,   g_wh_sqkv);
    cudaGetSymbolAddress((void**)&wso,   g_wh_sout);
    cudaGetSymbolAddress((void**)&ww1,   g_wh_w1);
    cudaGetSymbolAddress((void**)&ww2,   g_wh_w2);

    cudaFuncSetAttribute(tc_gemm_kernel,
                         cudaFuncAttributeMaxDynamicSharedMemorySize, TCG_SMEM);

    // weight convert+transpose
    convw_kernel<<<dim3(QKVW / 32, MM / 32), dim3(32, 8)>>>(t_qkv, wtq, MM, QKVW);
    convw_kernel<<<dim3(MM / 32, MM / 32), dim3(32, 8)>>>(t_out, wto, MM, MM);
    convw_kernel<<<dim3(MM / 32, MM / 32), dim3(32, 8)>>>(t_fc_w, wtf, MM, MM);
    convw_kernel<<<dim3(QKVW / 32, MM / 32), dim3(32, 8)>>>(s_qkv, wsq, MM, QKVW);
    convw_kernel<<<dim3(MM / 32, MM / 32), dim3(32, 8)>>>(s_out, wso, MM, MM);
    convw_kernel<<<dim3(MLPW / 32, MM / 32), dim3(32, 8)>>>(mlp_w1, ww1, MM, MLPW);
    convw_kernel<<<dim3(MM / 32, MLPW / 32), dim3(32, 8)>>>(mlp_w2, ww2, MLPW, MM);

    ada_kernel<<<dim3(ADAW / 128, BB), 128>>>(c4t, W_ada, b_ada);
    rope_kernel<<<1, TT * (DD / 2)>>>(f);
    ekv_kernel<<<dim3(BB * TT, 4), 256>>>(c, t_k, t_v, s_k, s_v);

    // temporal branch
    ln_kernel<<<ROWS, 256>>>(x, plnh, px4, tn_w, tn_b, nullptr, 0, 0, 1e-5f, 1);
    tc_gemm_kernel<<<dim3(QKVW / 128, ROWS / 128), 256, TCG_SMEM>>>(
        plnh, wtq, nullptr, nullptr, nullptr, nullptr, pbigh, MM, QKVW, 0, 0);
    attn_t_kernel<<<dim3(HH, NN, BB), 256>>>();
    tc_gemm_kernel<<<dim3(MM / 128, ROWS / 128), 256, TCG_SMEM>>>(
        pattnh, wto, nullptr, nullptr, nullptr, nullptr, plnh, MM, MM, 0, 1);
    tc_gemm_kernel<<<dim3(MM / 128, ROWS / 128), 256, TCG_SMEM>>>(
        plnh, wtf, t_fc_b, px4, nullptr, px4, nullptr, MM, MM, 0, 0);

    // spatial branch
    ln_kernel<<<ROWS, 256>>>(px4, plnh, nullptr, nullptr, nullptr, pada, 0, MM, 1e-6f, 0);
    tc_gemm_kernel<<<dim3(QKVW / 128, ROWS / 128), 256, TCG_SMEM>>>(
        plnh, wsq, nullptr, nullptr, nullptr, nullptr, pbigh, MM, QKVW, 0, 0);
    attn_s_kernel<<<dim3(HH, TT, BB), 256>>>();
    tc_gemm_kernel<<<dim3(MM / 128, ROWS / 128), 256, TCG_SMEM>>>(
        pattnh, wso, nullptr, px4, pada + 2 * MM, px4, nullptr, MM, MM, 0, 0);

    // MLP
    ln_kernel<<<ROWS, 256>>>(px4, plnh, nullptr, nullptr, nullptr, pada, 3 * MM, 4 * MM, 1e-6f, 0);
    tc_gemm_kernel<<<dim3(MLPW / 128, ROWS / 128), 256, TCG_SMEM>>>(
        plnh, ww1, mlp_b1, nullptr, nullptr, nullptr, pbigh, MM, MLPW, 1, 0);
    tc_gemm_kernel<<<dim3(MM / 128, ROWS / 128), 256, TCG_SMEM>>>(
        pbigh, ww2, mlp_b2, px4, pada + 5 * MM, out, nullptr, MLPW, MM, 0, 0);
}

// round 13
// speedup vs baseline: 4.2197x; 1.0194x over previous
#include <cuda_runtime.h>
#include <cuda_fp16.h>
#include <cstdint>

#define BB 2
#define TT 16
#define NN 256
#define MM 1152
#define HH 16
#define DD 72
#define ROWS 8192
#define ADAW 6912
#define QKVW 3456
#define MLPW 4608
#define SCALE 0.11785113019775793f

// ---------------- scratch -----------------------------------------------
__device__ float  g_x4[ROWS * MM];
__device__ __half g_lnh[ROWS * MM];
__device__ __half g_attnh[ROWS * MM];
__device__ __half g_bigh[(size_t)ROWS * MLPW];
__device__ float  g_ada[BB * ADAW];
__device__ float  g_tk[BB * TT * MM];
__device__ float  g_tv[BB * TT * MM];
__device__ float  g_sk[BB * TT * MM];
__device__ float  g_sv[BB * TT * MM];
__device__ float  g_ropec[TT * (DD / 2)];
__device__ float  g_ropes[TT * (DD / 2)];
// half weights
__device__ __half g_wh_tqkv[(size_t)QKVW * MM];   // [N][K]
__device__ __half g_wh_toutrm[(size_t)MM * MM];   // t_out row-major (convert only)
__device__ __half g_wh_tfc[(size_t)MM * MM];      // t_fc^T [N][K]
__device__ __half g_wh_comb[(size_t)MM * MM];     // (t_out@t_fc)^T [N][K]
__device__ __half g_wh_sqkv[(size_t)QKVW * MM];
__device__ __half g_wh_sout[(size_t)MM * MM];
__device__ __half g_wh_w1[(size_t)MLPW * MM];
__device__ __half g_wh_w2[(size_t)MM * MLPW];

// ---------------- helpers -------------------------------------------------
__device__ __forceinline__ uint32_t s2u(const void* p) {
    uint32_t a;
    asm("{ .reg .u64 t; cvta.to.shared.u64 t, %1; cvt.u32.u64 %0, t; }"
        : "=r"(a) : "l"(p));
    return a;
}
__device__ __forceinline__ void cpa16(void* s, const void* g) {
    asm volatile("cp.async.cg.shared.global [%0], [%1], 16;" :: "r"(s2u(s)), "l"(g));
}
__device__ __forceinline__ void ldsm4(uint32_t* r, const void* p) {
    asm volatile("ldmatrix.sync.aligned.m8n8.x4.shared.b16 {%0,%1,%2,%3}, [%4];"
        : "=r"(r[0]), "=r"(r[1]), "=r"(r[2]), "=r"(r[3]) : "r"(s2u(p)));
}
__device__ __forceinline__ void mma16816(float* d, const uint32_t* a, const uint32_t* b) {
    asm volatile(
        "mma.sync.aligned.m16n8k16.row.col.f32.f16.f16.f32 "
        "{%0,%1,%2,%3},{%4,%5,%6,%7},{%8,%9},{%0,%1,%2,%3};"
        : "+f"(d[0]), "+f"(d[1]), "+f"(d[2]), "+f"(d[3])
        : "r"(a[0]), "r"(a[1]), "r"(a[2]), "r"(a[3]), "r"(b[0]), "r"(b[1]));
}

// ---------------- weight transpose+convert [K,N]f32 -> [N,K]h ------------
__global__ __launch_bounds__(256) void convw_kernel(
    const float* __restrict__ S, __half* __restrict__ D, int K, int N)
{
    __shared__ float t[32][33];
    int x = blockIdx.x * 32 + threadIdx.x;
    int y0 = blockIdx.y * 32;
#pragma unroll
    for (int j = threadIdx.y; j < 32; j += 8)
        t[j][threadIdx.x] = S[(size_t)(y0 + j) * N + x];
    __syncthreads();
    int x2 = y0 + threadIdx.x;
    int y2 = blockIdx.x * 32;
#pragma unroll
    for (int j = threadIdx.y; j < 32; j += 8)
        D[(size_t)(y2 + j) * K + x2] = __float2half(t[threadIdx.x][j]);
}

// ---------------- plain convert f32 -> half (same layout) ------------------
__global__ __launch_bounds__(256) void convh_kernel(
    const float* __restrict__ S, __half* __restrict__ D, int total)
{
    int i = blockIdx.x * 256 + threadIdx.x;
    if (i < total) D[i] = __float2half(S[i]);
}

// ---------------- fp16 mma GEMM: CTA 128x128, warp 32x64, Kc=32 ----------
// 4-stage cp.async ring (wait -> barrier -> prefetch -> compute), ldmatrix,
// 2 CTAs/SM. smem row stride 40 halves (80B): ldsm rows partition banks.
#define HSTR 40
#define TILE_H (128 * HSTR)            // halves per operand tile
#define STAGE_H (2 * TILE_H)           // A + B
#define NSTG 4
#define TCG_SMEM (NSTG * STAGE_H * 2)  // bytes (80 KB)
__global__ __launch_bounds__(256, 2) void tc_gemm_kernel(
    const __half* __restrict__ A, const __half* __restrict__ W,
    const float* __restrict__ bias, const float* __restrict__ addsrc,
    const float* __restrict__ gate,
    float* __restrict__ Cf, __half* __restrict__ Ch,
    int K, int Nc, int act, int permute)
{
    extern __shared__ __half smem[];
    int tid = threadIdx.x, lane = tid & 31, wid = tid >> 5;
    int wm = wid & 3, wn = wid >> 2;
    int qrow = lane >> 2, qk = lane & 3;
    int blockCol = blockIdx.x * 128, blockRow = blockIdx.y * 128;
    int nc = K >> 5;

    float acc[2][8][4];
#pragma unroll
    for (int mt = 0; mt < 2; mt++)
#pragma unroll
        for (int nt = 0; nt < 8; nt++)
#pragma unroll
            for (int r = 0; r < 4; r++) acc[mt][nt][r] = 0.f;

    // cp.async plan: per chunk, each operand = 512 16B segs; row=seg>>2, s=seg&3
    int a0 = tid, a1 = tid + 256;
    int ar0 = a0 >> 2, as0 = a0 & 3, ar1 = a1 >> 2, as1 = a1 & 3;
    const __half* Ab = A + (size_t)blockRow * K;
    const __half* Bb = W + (size_t)blockCol * K;

    // ldmatrix addresses (half offsets within tile)
    int amrow = wm * 32 + (lane & 15);
    int akoff = (lane >> 4) << 3;
    int bnrow = wn * 64 + (lane & 7) + ((lane >> 4) << 3);
    int bkoff = ((lane >> 3) & 1) << 3;

#define PREFETCH(chunk, stg_) do {                                              \
    __half* As_ = smem + (stg_) * STAGE_H;                                       \
    __half* Bs_ = As_ + TILE_H;                                                  \
    int k0 = (chunk) << 5;                                                       \
    cpa16(As_ + ar0 * HSTR + as0 * 8, Ab + (size_t)ar0 * K + k0 + as0 * 8);      \
    cpa16(As_ + ar1 * HSTR + as1 * 8, Ab + (size_t)ar1 * K + k0 + as1 * 8);      \
    cpa16(Bs_ + ar0 * HSTR + as0 * 8, Bb + (size_t)ar0 * K + k0 + as0 * 8);      \
    cpa16(Bs_ + ar1 * HSTR + as1 * 8, Bb + (size_t)ar1 * K + k0 + as1 * 8);      \
    asm volatile("cp.async.commit_group;" ::: "memory");                         \
} while (0)

    PREFETCH(0, 0);
    if (nc > 1) PREFETCH(1, 1);
    if (nc > 2) PREFETCH(2, 2);

    int stg = 0;
#pragma unroll 1
    for (int i = 0; i < nc; i++) {
        // retire my copies for chunk i (allow up to 2 younger groups in flight)
        int rem = nc - 1 - i;
        if (rem >= 2)      asm volatile("cp.async.wait_group 2;" ::: "memory");
        else if (rem == 1) asm volatile("cp.async.wait_group 1;" ::: "memory");
        else               asm volatile("cp.async.wait_group 0;" ::: "memory");
        // ALL threads' copies for chunk i done; reads of stage (i-1) done:
        __syncthreads();
        if (i + 3 < nc)
            PREFETCH(i + 3, (stg == 0) ? (NSTG - 1) : stg - 1);  // stage (i-1)%4
        const __half* As = smem + stg * STAGE_H;
        const __half* Bs = As + TILE_H;
#pragma unroll
        for (int kk = 0; kk < 2; kk++) {
            int kb = kk * 16;
            uint32_t a[2][4], b[4][4];
            ldsm4(a[0], As + amrow * HSTR + kb + akoff);
            ldsm4(a[1], As + (amrow + 16) * HSTR + kb + akoff);
#pragma unroll
            for (int ntp = 0; ntp < 4; ntp++)
                ldsm4(b[ntp], Bs + (bnrow + ntp * 16) * HSTR + kb + bkoff);
#pragma unroll
            for (int mt = 0; mt < 2; mt++)
#pragma unroll
                for (int ntp = 0; ntp < 4; ntp++) {
                    mma16816(acc[mt][2 * ntp],     a[mt], &b[ntp][0]);
                    mma16816(acc[mt][2 * ntp + 1], a[mt], &b[ntp][2]);
                }
        }
        stg = (stg + 1 >= NSTG) ? 0 : stg + 1;
    }

    // epilogue: d0:(r,c) d1:(r,c+1) d2:(r+8,c) d3:(r+8,c+1)
#pragma unroll
    for (int mt = 0; mt < 2; mt++) {
#pragma unroll
        for (int half = 0; half < 2; half++) {
            int row = blockRow + wm * 32 + mt * 16 + qrow + half * 8;
            int bch = row >> 12;
            int orow = row;
            if (permute) {
                int rem = row & 4095;
                orow = ((bch << 4) + (rem & 15)) * NN + (rem >> 4);
            }
            float* crow = Cf ? Cf + (size_t)orow * Nc : nullptr;
            __half* hrow = Ch ? Ch + (size_t)orow * Nc : nullptr;
            const float* arow = addsrc ? addsrc + (size_t)orow * Nc : nullptr;
#pragma unroll
            for (int nt = 0; nt < 8; nt++) {
#pragma unroll
                for (int e = 0; e < 2; e++) {
                    int col = blockCol + wn * 64 + nt * 8 + 2 * qk + e;
                    float v = acc[mt][nt][half * 2 + e];
                    if (bias) v += bias[col];
                    if (act) {
                        float xg = v;
                        v = 0.5f * xg * (1.f + tanhf(0.7978845608028654f *
                                (xg + 0.044715f * xg * xg * xg)));
                    }
                    if (gate) v *= gate[bch * ADAW + col];
                    if (arow) v += arow[col];
                    if (crow) crow[col] = v;
                    if (hrow) hrow[col] = __float2half(v);
                }
            }
        }
    }
}

// ---------------- ada = silu(c4t) @ W_ada + b_ada -------------------------
__global__ __launch_bounds__(128) void ada_kernel(
    const float* __restrict__ c4t, const float* __restrict__ W,
    const float* __restrict__ bias)
{
    __shared__ float ss[MM];
    int b = blockIdx.y;
    for (int i = threadIdx.x; i < MM; i += 128) {
        float v = c4t[b * MM + i];
        ss[i] = v / (1.f + expf(-v));
    }
    __syncthreads();
    int col = blockIdx.x * 128 + threadIdx.x;
    float acc = bias[col];
    for (int k = 0; k < MM; k++)
        acc += ss[k] * W[(size_t)k * ADAW + col];
    g_ada[b * ADAW + col] = acc;
}

// ---------------- rope tables ---------------------------------------------
__global__ void rope_kernel(const int* __restrict__ f)
{
    int idx = threadIdx.x;
    if (idx < TT * (DD / 2)) {
        int t = idx / (DD / 2), i = idx % (DD / 2);
        float pos = (float)f[t];
        float freq = powf(10000.f, -((2.f * (float)i) / (float)DD));
        float a = pos * freq;
        g_ropec[idx] = cosf(a);
        g_ropes[idx] = sinf(a);
    }
}

// ---------------- extra-KV projections ------------------------------------
__global__ __launch_bounds__(256) void ekv_kernel(
    const float* __restrict__ c,
    const float* __restrict__ tk, const float* __restrict__ tv,
    const float* __restrict__ sk, const float* __restrict__ sv)
{
    __shared__ float cs[MM];
    int row = blockIdx.x;
    int which = blockIdx.y;
    const float* W = (which == 0) ? tk : (which == 1) ? tv : (which == 2) ? sk : sv;
    float* O = (which == 0) ? g_tk : (which == 1) ? g_tv : (which == 2) ? g_sk : g_sv;
    for (int i = threadIdx.x; i < MM; i += 256) cs[i] = c[(size_t)row * MM + i];
    __syncthreads();
    for (int col = threadIdx.x; col < MM; col += 256) {
        float acc = 0.f;
        for (int k = 0; k < MM; k++)
            acc += cs[k] * W[(size_t)k * MM + col];
        O[(size_t)row * MM + col] = acc;
    }
}

// ---------------- LayerNorm (half output) ----------------------------------
__global__ __launch_bounds__(256) void ln_kernel(
    const float* __restrict__ X, __half* __restrict__ out, float* __restrict__ copyDst,
    const float* __restrict__ w, const float* __restrict__ bvec,
    const float* __restrict__ ada, int shOff, int scOff, float eps, int permute)
{
    int row = blockIdx.x;
    const float* xr = X + (size_t)row * MM;
    float xv[5];
    float s = 0.f, sq = 0.f;
    int k = 0;
    for (int i = threadIdx.x; i < MM; i += 256, k++) {
        float v = xr[i];
        xv[k] = v;
        s += v; sq += v * v;
    }
    __shared__ float reds[8], redq[8], stats[2];
    for (int off = 16; off > 0; off >>= 1) {
        s  += __shfl_xor_sync(0xffffffffu, s,  off);
        sq += __shfl_xor_sync(0xffffffffu, sq, off);
    }
    int wid = threadIdx.x >> 5, lane = threadIdx.x & 31;
    if (lane == 0) { reds[wid] = s; redq[wid] = sq; }
    __syncthreads();
    if (threadIdx.x == 0) {
        float ts = 0.f, tq = 0.f;
        for (int i2 = 0; i2 < 8; i2++) { ts += reds[i2]; tq += redq[i2]; }
        float mean = ts * (1.f / MM);
        float var = tq * (1.f / MM) - mean * mean;
        stats[0] = mean;
        stats[1] = rsqrtf(var + eps);
    }
    __syncthreads();
    float mean = stats[0], rstd = stats[1];
    int b = row >> 12;
    int orow = row;
    if (permute) {
        int rem = row & 4095;
        int t = rem >> 8, n = rem & 255;
        orow = ((b << 8) + n) * TT + t;
    }
    k = 0;
    for (int i = threadIdx.x; i < MM; i += 256, k++) {
        float v = xv[k];
        float nv = (v - mean) * rstd;
        float y;
        if (ada) y = nv * (1.f + ada[b * ADAW + scOff + i]) + ada[b * ADAW + shOff + i];
        else     y = nv * w[i] + bvec[i];
        out[(size_t)orow * MM + i] = __float2half(y);
        if (copyDst) copyDst[(size_t)row * MM + i] = v;
    }
}

// ---------------- temporal attention (half qkv in, half out) ---------------
__global__ __launch_bounds__(256) void attn_t_kernel()
{
    __shared__ float qs[TT * DD];
    __shared__ float kks[2 * TT * DD];
    __shared__ float vvs[2 * TT * DD];
    __shared__ float scs[TT * 2 * TT];
    int h = blockIdx.x, n = blockIdx.y, b = blockIdx.z;
    const __half* base = g_bigh + (size_t)((b * NN + n) * TT) * QKVW + h * DD;

    for (int idx = threadIdx.x; idx < TT * (DD / 2); idx += 256) {
        int t = idx / (DD / 2), i = idx % (DD / 2);
        float cc = g_ropec[idx], ssn = g_ropes[idx];
        const __half* qr = base + (size_t)t * QKVW + 2 * i;
        float x0 = __half2float(qr[0]), x1 = __half2float(qr[1]);
        qs[t * DD + 2 * i]     = SCALE * (x0 * cc - x1 * ssn);
        qs[t * DD + 2 * i + 1] = SCALE * (x1 * cc + x0 * ssn);
        const __half* kr = qr + MM;
        x0 = __half2float(kr[0]); x1 = __half2float(kr[1]);
        kks[(TT + t) * DD + 2 * i]     = x0 * cc - x1 * ssn;
        kks[(TT + t) * DD + 2 * i + 1] = x1 * cc + x0 * ssn;
        const float* er = g_tk + (size_t)(b * TT + t) * MM + h * DD + 2 * i;
        x0 = er[0]; x1 = er[1];
        kks[t * DD + 2 * i]     = x0 * cc - x1 * ssn;
        kks[t * DD + 2 * i + 1] = x1 * cc + x0 * ssn;
    }
    for (int idx = threadIdx.x; idx < TT * DD; idx += 256) {
        int t = idx / DD, d = idx % DD;
        vvs[(TT + t) * DD + d] = __half2float(base[(size_t)t * QKVW + 2 * MM + d]);
        vvs[t * DD + d] = g_tv[(size_t)(b * TT + t) * MM + h * DD + d];
    }
    __syncthreads();

    for (int idx = threadIdx.x; idx < TT * 2 * TT; idx += 256) {
        int t = idx / (2 * TT), j = idx % (2 * TT);
        float acc = 0.f;
#pragma unroll
        for (int d = 0; d < DD; d++) acc += qs[t * DD + d] * kks[j * DD + d];
        scs[idx] = acc;
    }
    __syncthreads();

    if (threadIdx.x < TT) {
        int t = threadIdx.x;
        float m = -1e30f;
        for (int j = 0; j < 2 * TT; j++) m = fmaxf(m, scs[t * 2 * TT + j]);
        float sum = 0.f;
        for (int j = 0; j < 2 * TT; j++) {
            float p = __expf(scs[t * 2 * TT + j] - m);
            scs[t * 2 * TT + j] = p;
            sum += p;
        }
        float inv = 1.f / sum;
        for (int j = 0; j < 2 * TT; j++) scs[t * 2 * TT + j] *= inv;
    }
    __syncthreads();

    for (int idx = threadIdx.x; idx < TT * DD; idx += 256) {
        int t = idx / DD, d = idx % DD;
        float acc = 0.f;
#pragma unroll
        for (int j = 0; j < 2 * TT; j++) acc += scs[t * 2 * TT + j] * vvs[j * DD + d];
        g_attnh[(size_t)((b * NN + n) * TT + t) * MM + h * DD + d] = __float2half(acc);
    }
}

// ---------------- spatial attention: online softmax, smem KV tiles ---------
#define SKV 64
__global__ __launch_bounds__(256) void attn_s_kernel()
{
    __shared__ __half kt[SKV * DD];
    __shared__ __half vt[SKV * DD];
    int h = blockIdx.x, t = blockIdx.y, b = blockIdx.z;
    int n = threadIdx.x;
    const __half* base = g_bigh + (size_t)((b * TT + t) * NN) * QKVW;

    uint32_t q2[DD / 2];
    {
        const uint32_t* qr = (const uint32_t*)(base + (size_t)n * QKVW + h * DD);
#pragma unroll
        for (int i = 0; i < DD / 2; i++) q2[i] = qr[i];
    }
    float acc[DD];
#pragma unroll
    for (int d = 0; d < DD; d++) acc[d] = 0.f;
    float mcur = -1e30f, lsum = 0.f;

    for (int tile = 0; tile < (NN + 1 + SKV - 1) / SKV; tile++) {
        int j0 = tile * SKV;
        int jcount = (NN + 1) - j0;
        if (jcount > SKV) jcount = SKV;
        __syncthreads();
        for (int idx = threadIdx.x; idx < jcount * (DD / 2); idx += 256) {
            int jj = idx / (DD / 2), dp = idx % (DD / 2);
            int j = j0 + jj;
            __half2 kv2, vv2;
            if (j == 0) {
                const float* kf = g_sk + (size_t)(b * TT + t) * MM + h * DD + 2 * dp;
                const float* vf = g_sv + (size_t)(b * TT + t) * MM + h * DD + 2 * dp;
                kv2 = __floats2half2_rn(kf[0], kf[1]);
                vv2 = __floats2half2_rn(vf[0], vf[1]);
            } else {
                const __half* krow = base + (size_t)(j - 1) * QKVW + MM + h * DD;
                const __half* vrow = base + (size_t)(j - 1) * QKVW + 2 * MM + h * DD;
                kv2 = *(const __half2*)(krow + 2 * dp);
                vv2 = *(const __half2*)(vrow + 2 * dp);
            }
            *(__half2*)&kt[jj * DD + 2 * dp] = kv2;
            *(__half2*)&vt[jj * DD + 2 * dp] = vv2;
        }
        __syncthreads();

        for (int jj = 0; jj < jcount; jj++) {
            float s = 0.f;
#pragma unroll
            for (int i = 0; i < DD / 2; i++) {
                float2 kp = __half22float2(*(const __half2*)&kt[jj * DD + 2 * i]);
                float2 qp = __half22float2(*(const __half2*)&q2[i]);
                s += qp.x * kp.x + qp.y * kp.y;
            }
            s *= SCALE;
            if (s > mcur) {
                float c = __expf(mcur - s);
                lsum *= c;
#pragma unroll
                for (int d = 0; d < DD; d++) acc[d] *= c;
                mcur = s;
            }
            float p = __expf(s - mcur);
            lsum += p;
#pragma unroll
            for (int i = 0; i < DD / 2; i++) {
                float2 vp = __half22float2(*(const __half2*)&vt[jj * DD + 2 * i]);
                acc[2 * i]     += p * vp.x;
                acc[2 * i + 1] += p * vp.y;
            }
        }
    }
    float inv = 1.f / lsum;
    __half* orow = g_attnh + (size_t)((b * TT + t) * NN + n) * MM + h * DD;
#pragma unroll
    for (int d = 0; d < DD; d++) orow[d] = __float2half(acc[d] * inv);
}

// ---------------- launch ----------------------------------------------------
extern "C" void kernel_launch(void* const* d_in, const int* in_sizes, int n_in,
                              void* d_out, int out_size)
{
    (void)in_sizes; (void)n_in; (void)out_size;
    const float* x      = (const float*)d_in[0];
    const float* c4t    = (const float*)d_in[1];
    const float* c      = (const float*)d_in[2];
    const float* W_ada  = (const float*)d_in[3];
    const float* b_ada  = (const float*)d_in[4];
    const float* tn_w   = (const float*)d_in[5];
    const float* tn_b   = (const float*)d_in[6];
    const float* t_qkv  = (const float*)d_in[7];
    const float* t_k    = (const float*)d_in[8];
    const float* t_v    = (const float*)d_in[9];
    const float* t_out  = (const float*)d_in[10];
    const float* t_fc_w = (const float*)d_in[11];
    const float* t_fc_b = (const float*)d_in[12];
    const float* s_qkv  = (const float*)d_in[13];
    const float* s_k    = (const float*)d_in[14];
    const float* s_v    = (const float*)d_in[15];
    const float* s_out  = (const float*)d_in[16];
    const float* mlp_w1 = (const float*)d_in[17];
    const float* mlp_b1 = (const float*)d_in[18];
    const float* mlp_w2 = (const float*)d_in[19];
    const float* mlp_b2 = (const float*)d_in[20];
    const int*   f      = (const int*)d_in[21];
    float* out = (float*)d_out;

    float *px4, *pada;
    __half *plnh, *pattnh, *pbigh;
    __half *wtq, *wtoutrm, *wtf, *wcomb, *wsq, *wso, *ww1, *ww2;
    cudaGetSymbolAddress((void**)&px4,    g_x4);
    cudaGetSymbolAddress((void**)&pada,   g_ada);
    cudaGetSymbolAddress((void**)&plnh,   g_lnh);
    cudaGetSymbolAddress((void**)&pattnh, g_attnh);
    cudaGetSymbolAddress((void**)&pbigh,  g_bigh);
    cudaGetSymbolAddress((void**)&wtq,    g_wh_tqkv);
    cudaGetSymbolAddress((void**)&wtoutrm,g_wh_toutrm);
    cudaGetSymbolAddress((void**)&wtf,    g_wh_tfc);
    cudaGetSymbolAddress((void**)&wcomb,  g_wh_comb);
    cudaGetSymbolAddress((void**)&wsq,    g_wh_sqkv);
    cudaGetSymbolAddress((void**)&wso,    g_wh_sout);
    cudaGetSymbolAddress((void**)&ww1,    g_wh_w1);
    cudaGetSymbolAddress((void**)&ww2,    g_wh_w2);

    cudaFuncSetAttribute(tc_gemm_kernel,
                         cudaFuncAttributeMaxDynamicSharedMemorySize, TCG_SMEM);

    // weight convert/transpose
    convw_kernel<<<dim3(QKVW / 32, MM / 32), dim3(32, 8)>>>(t_qkv, wtq, MM, QKVW);
    convh_kernel<<<(MM * MM + 255) / 256, 256>>>(t_out, wtoutrm, MM * MM);
    convw_kernel<<<dim3(MM / 32, MM / 32), dim3(32, 8)>>>(t_fc_w, wtf, MM, MM);
    convw_kernel<<<dim3(QKVW / 32, MM / 32), dim3(32, 8)>>>(s_qkv, wsq, MM, QKVW);
    convw_kernel<<<dim3(MM / 32, MM / 32), dim3(32, 8)>>>(s_out, wso, MM, MM);
    convw_kernel<<<dim3(MLPW / 32, MM / 32), dim3(32, 8)>>>(mlp_w1, ww1, MM, MLPW);
    convw_kernel<<<dim3(MM / 32, MLPW / 32), dim3(32, 8)>>>(mlp_w2, ww2, MLPW, MM);

    // Wc^T[n][k0] = sum_j t_fc^T[n][j] * t_out[k0][j]  -> combined weight [N][K]
    tc_gemm_kernel<<<dim3(MM / 128, MM / 128), 256, TCG_SMEM>>>(
        wtf, wtoutrm, nullptr, nullptr, nullptr, nullptr, wcomb, MM, MM, 0, 0);

    ada_kernel<<<dim3(ADAW / 128, BB), 128>>>(c4t, W_ada, b_ada);
    rope_kernel<<<1, TT * (DD / 2)>>>(f);
    ekv_kernel<<<dim3(BB * TT, 4), 256>>>(c, t_k, t_v, s_k, s_v);

    // temporal branch
    ln_kernel<<<ROWS, 256>>>(x, plnh, px4, tn_w, tn_b, nullptr, 0, 0, 1e-5f, 1);
    tc_gemm_kernel<<<dim3(QKVW / 128, ROWS / 128), 256, TCG_SMEM>>>(
        plnh, wtq, nullptr, nullptr, nullptr, nullptr, pbigh, MM, QKVW, 0, 0);
    attn_t_kernel<<<dim3(HH, NN, BB), 256>>>();
    // fused (attn @ t_out) @ t_fc_w + b + x4, permuted rows
    tc_gemm_kernel<<<dim3(MM / 128, ROWS / 128), 256, TCG_SMEM>>>(
        pattnh, wcomb, t_fc_b, px4, nullptr, px4, nullptr, MM, MM, 0, 1);

    // spatial branch
    ln_kernel<<<ROWS, 256>>>(px4, plnh, nullptr, nullptr, nullptr, pada, 0, MM, 1e-6f, 0);
    tc_gemm_kernel<<<dim3(QKVW / 128, ROWS / 128), 256, TCG_SMEM>>>(
        plnh, wsq, nullptr, nullptr, nullptr, nullptr, pbigh, MM, QKVW, 0, 0);
    attn_s_kernel<<<dim3(HH, TT, BB), 256>>>();
    tc_gemm_kernel<<<dim3(MM / 128, ROWS / 128), 256, TCG_SMEM>>>(
        pattnh, wso, nullptr, px4, pada + 2 * MM, px4, nullptr, MM, MM, 0, 0);

    // MLP
    ln_kernel<<<ROWS, 256>>>(px4, plnh, nullptr, nullptr, nullptr, pada, 3 * MM, 4 * MM, 1e-6f, 0);
    tc_gemm_kernel<<<dim3(MLPW / 128, ROWS / 128), 256, TCG_SMEM>>>(
        plnh, ww1, mlp_b1, nullptr, nullptr, nullptr, pbigh, MM, MLPW, 1, 0);
    tc_gemm_kernel<<<dim3(MM / 128, ROWS / 128), 256, TCG_SMEM>>>(
        pbigh, ww2, mlp_b2, px4, pada + 5 * MM, out, nullptr, MLPW, MM, 0, 0);
}